// round 14
// baseline (speedup 1.0000x reference)
#include <cuda_runtime.h>
#include <cuda_bf16.h>
#include <math.h>
#include <stdint.h>

// ---- arch-specific gate: tcgen05 only exists in the sm_103a cubin pass ----
#if defined(__CUDA_ARCH__)
#  if defined(__CUDA_ARCH_FEAT_SM103_ALL) || defined(__CUDA_ARCH_FEAT_SM101_ALL) || \
      defined(__CUDA_ARCH_FEAT_SM100_ALL) || defined(__CUDA_ARCH_SPECIFIC__) ||     \
      defined(__CUDA_ARCH_FAMILY_SPECIFIC__)
#    define TC_PATH 1
#  else
#    define TC_PATH 0
#  endif
#else
#  define TC_PATH 0
#endif

// ---------------- problem dims ----------------
#define BB   4096
#define TT   35
#define DSE  227
#define SE   163
#define CC   64
#define HH   1024
#define G5   25
#define SS   12
#define OUTW 415

#define KREAL (64 + TT*SE)   // 5769
#define KCOMB 5824           // multiple of 64 (364 chunks of 16)
#define DSEP  256
#define NF3   384
#define NC3   128

// ---------------- scratch ----------------
#define PLANES2(name, sz) \
    __device__ __align__(16) __nv_bfloat16 name##_0[sz]; \
    __device__ __align__(16) __nv_bfloat16 name##_1[sz];

PLANES2(g_Ac,  BB * KCOMB)
PLANES2(g_ch1, BB * HH)
PLANES2(g_ch2, BB * HH)
PLANES2(g_fin, BB * DSEP)
PLANES2(g_fh1, BB * HH)
PLANES2(g_fh2, BB * HH)
PLANES2(g_Br,  DSEP * KCOMB)
PLANES2(g_c1w, HH * 64)
PLANES2(g_c2w, HH * HH)
PLANES2(g_c3w, NC3 * HH)
PLANES2(g_f1w, HH * DSEP)
PLANES2(g_f2w, HH * HH)
PLANES2(g_f3w, NF3 * HH)

__device__ __align__(16) float d_ep0[BB * DSEP];
__device__ __align__(16) float d_ep1[BB * DSEP];
__device__ __align__(16) float d_ep2[BB * DSEP];
__device__ float d_fout[BB * NF3];
__device__ float d_cout[BB * NC3];
__device__ float d_gout[BB * NF3];
__device__ float d_gc[DSE * 5];
__device__ float d_fbias[NF3];
__device__ float d_cbias[NC3];

// ---------------- math helpers ----------------
__device__ __forceinline__ float softplusf(float x) {
    return fmaxf(x, 0.f) + __logf(1.f + __expf(-fabsf(x)));
}
__device__ __forceinline__ void split2(float v, __nv_bfloat16& p0, __nv_bfloat16& p1) {
    p0 = __float2bfloat16(v);
    p1 = __float2bfloat16(v - __bfloat162float(p0));
}

// ---------------- PTX helpers ----------------
__device__ __forceinline__ uint32_t smem_u32(const void* p) {
    uint32_t a;
    asm("{ .reg .u64 t; cvta.to.shared.u64 t, %1; cvt.u32.u64 %0, t; }" : "=r"(a) : "l"(p));
    return a;
}
__device__ __forceinline__ void mbar_init(uint32_t addr, uint32_t cnt) {
    asm volatile("mbarrier.init.shared.b64 [%0], %1;" :: "r"(addr), "r"(cnt) : "memory");
}
__device__ __forceinline__ void mbar_wait(uint32_t addr, uint32_t parity) {
    uint32_t done;
    asm volatile("{\n\t.reg .pred p;\n\t"
        "mbarrier.try_wait.parity.acquire.cta.shared::cta.b64 p, [%1], %2;\n\t"
        "selp.b32 %0, 1, 0, p;\n\t}"
        : "=r"(done) : "r"(addr), "r"(parity) : "memory");
    while (!done) {
        asm volatile("{\n\t.reg .pred p;\n\t"
            "mbarrier.try_wait.parity.acquire.cta.shared::cta.b64 p, [%1], %2, 0x989680;\n\t"
            "selp.b32 %0, 1, 0, p;\n\t}"
            : "=r"(done) : "r"(addr), "r"(parity) : "memory");
    }
}
__device__ __forceinline__ void fence_proxy_async_cta() {
    asm volatile("fence.proxy.async.shared::cta;" ::: "memory");
}
__device__ __forceinline__ void cp_async16(uint32_t dst, const void* src) {
    asm volatile("cp.async.cg.shared.global [%0], [%1], 16;" :: "r"(dst), "l"(src) : "memory");
}
// .noinc is load-bearing (default variant pre-increments -> R12 deadlock)
__device__ __forceinline__ void cp_async_mbar_arrive_noinc(uint32_t mbar) {
    asm volatile("cp.async.mbarrier.arrive.noinc.shared::cta.b64 [%0];" :: "r"(mbar) : "memory");
}

#if TC_PATH
__device__ __forceinline__ void tmem_alloc(uint32_t smem_dst, uint32_t ncols) {
    asm volatile("tcgen05.alloc.cta_group::1.sync.aligned.shared::cta.b32 [%0], %1;"
                 :: "r"(smem_dst), "r"(ncols) : "memory");
}
__device__ __forceinline__ void tmem_dealloc(uint32_t tmem, uint32_t ncols) {
    asm volatile("tcgen05.dealloc.cta_group::1.sync.aligned.b32 %0, %1;" :: "r"(tmem), "r"(ncols));
}
__device__ __forceinline__ void tmem_relinquish() {
    asm volatile("tcgen05.relinquish_alloc_permit.cta_group::1.sync.aligned;");
}
__device__ __forceinline__ void tc_commit(uint32_t mbar) {
    asm volatile("tcgen05.commit.cta_group::1.mbarrier::arrive::one.shared::cluster.b64 [%0];"
                 :: "r"(mbar) : "memory");
}
__device__ __forceinline__ void tc_fence_after() {
    asm volatile("tcgen05.fence::after_thread_sync;" ::: "memory");
}
__device__ __forceinline__ void mma_f16_ss(uint32_t d, uint64_t ad, uint64_t bd,
                                           uint32_t idesc, int acc) {
    asm volatile("{\n\t.reg .pred p;\n\tsetp.ne.u32 p, %5, 0;\n\t"
        "tcgen05.mma.cta_group::1.kind::f16 [%0], %1, %2, %3, {%4, %4, %4, %4}, p;\n\t}"
        :: "r"(d), "l"(ad), "l"(bd), "r"(idesc), "r"(0u), "r"((uint32_t)acc) : "memory");
}
#define TC_LD_X32(r, addr) \
    asm volatile("tcgen05.ld.sync.aligned.32x32b.x32.b32 " \
        "{%0, %1, %2, %3, %4, %5, %6, %7, %8, %9, %10, %11, %12, %13, %14, %15, " \
        " %16, %17, %18, %19, %20, %21, %22, %23, %24, %25, %26, %27, %28, %29, %30, %31}, [%32];" \
        : "=r"((r)[0]),  "=r"((r)[1]),  "=r"((r)[2]),  "=r"((r)[3]), \
          "=r"((r)[4]),  "=r"((r)[5]),  "=r"((r)[6]),  "=r"((r)[7]), \
          "=r"((r)[8]),  "=r"((r)[9]),  "=r"((r)[10]), "=r"((r)[11]), \
          "=r"((r)[12]), "=r"((r)[13]), "=r"((r)[14]), "=r"((r)[15]), \
          "=r"((r)[16]), "=r"((r)[17]), "=r"((r)[18]), "=r"((r)[19]), \
          "=r"((r)[20]), "=r"((r)[21]), "=r"((r)[22]), "=r"((r)[23]), \
          "=r"((r)[24]), "=r"((r)[25]), "=r"((r)[26]), "=r"((r)[27]), \
          "=r"((r)[28]), "=r"((r)[29]), "=r"((r)[30]), "=r"((r)[31]) \
        : "r"(addr))
#define TC_WAIT_LD() asm volatile("tcgen05.wait::ld.sync.aligned;" ::: "memory")
#endif // TC_PATH

#define SW128(x) ((x) ^ (((x) >> 3) & 0x70))
#define SW32(x)  ((x) ^ (((x) >> 3) & 0x10))
static __device__ __forceinline__ uint64_t smem_desc_sw32(uint32_t addr) {
    // layout=6 (SW32), version=1 (Blackwell), SBO=16 (256B = 8 rows x 32B), LBO=1 (16B)
    const uint64_t base = (6ull << 61) | (1ull << 46) | (16ull << 32) | (1ull << 16);
    return base | (uint64_t)((addr >> 4) & 0x3FFF);
}

// ---------------- conversions ----------------
__global__ __launch_bounds__(256)
void conv_act_kernel(const float* __restrict__ pz, const float* __restrict__ se,
                     __nv_bfloat16* __restrict__ o0, __nv_bfloat16* __restrict__ o1)
{
    size_t g = (size_t)blockIdx.x * blockDim.x + threadIdx.x;
    if (g >= (size_t)BB * (KCOMB / 8)) return;
    int b = (int)(g / (KCOMB / 8));
    int c0 = (int)(g - (size_t)b * (KCOMB / 8)) * 8;

    float v[8];
#pragma unroll
    for (int i = 0; i < 8; i++) {
        int c = c0 + i;
        if (c < 64)          v[i] = __ldg(&pz[b * 64 + c]);
        else if (c < KREAL)  v[i] = __ldg(&se[(size_t)b * (TT*SE) + (c - 64)]);
        else                 v[i] = 0.f;
    }
    ushort h0[8], h1[8];
#pragma unroll
    for (int i = 0; i < 8; i++) {
        __nv_bfloat16 a, bq; split2(v[i], a, bq);
        h0[i] = __bfloat16_as_ushort(a);
        h1[i] = __bfloat16_as_ushort(bq);
    }
    size_t o = (size_t)b * KCOMB + c0;
    *(uint4*)(o0 + o) = *(uint4*)h0;
    *(uint4*)(o1 + o) = *(uint4*)h1;
}

__global__ __launch_bounds__(256)
void conv_w_t(const float* __restrict__ W,
              __nv_bfloat16* __restrict__ o0, __nv_bfloat16* __restrict__ o1,
              int Kreal, int Nreal, int Kpad)
{
    __shared__ float s[64][33];
    const int bk = blockIdx.x * 64;
    const int bn = blockIdx.y * 32;
    const int tx = threadIdx.x & 31;
    const int ty = threadIdx.x >> 5;

#pragma unroll
    for (int i = 0; i < 8; i++) {
        int cl = ty + i * 8;
        int k = bk + cl, n = bn + tx;
        float v = (k < Kreal && n < Nreal) ? W[(size_t)k * Nreal + n] : 0.f;
        s[cl][tx] = v;
    }
    __syncthreads();

    const int cl = threadIdx.x & 63;
    const int nb = threadIdx.x >> 6;
#pragma unroll
    for (int i = 0; i < 8; i++) {
        int nl = nb + i * 4;
        float v = s[cl][nl];
        __nv_bfloat16 a, b; split2(v, a, b);
        size_t o = (size_t)(bn + nl) * Kpad + bk + cl;
        o0[o] = a; o1[o] = b;
    }
}

struct CJob {
    const float* W;
    __nv_bfloat16 *o0, *o1;
    int Kreal, Nreal, Kpad, gx, end;
};
__global__ __launch_bounds__(256)
void conv_multi(CJob j0, CJob j1, CJob j2, CJob j3, CJob j4)
{
    CJob J; int start;
    int bid = blockIdx.x;
    if      (bid < j0.end) { J = j0; start = 0; }
    else if (bid < j1.end) { J = j1; start = j0.end; }
    else if (bid < j2.end) { J = j2; start = j1.end; }
    else if (bid < j3.end) { J = j3; start = j2.end; }
    else                   { J = j4; start = j3.end; }
    int local = bid - start;
    const int bk = (local % J.gx) * 64;
    const int bn = (local / J.gx) * 32;

    __shared__ float s[64][33];
    const int tx = threadIdx.x & 31;
    const int ty = threadIdx.x >> 5;
#pragma unroll
    for (int i = 0; i < 8; i++) {
        int cl = ty + i * 8;
        int k = bk + cl, n = bn + tx;
        float v = (k < J.Kreal && n < J.Nreal) ? J.W[(size_t)k * J.Nreal + n] : 0.f;
        s[cl][tx] = v;
    }
    __syncthreads();
    const int cl = threadIdx.x & 63;
    const int nb = threadIdx.x >> 6;
#pragma unroll
    for (int i = 0; i < 8; i++) {
        int nl = nb + i * 4;
        float v = s[cl][nl];
        __nv_bfloat16 a, b; split2(v, a, b);
        size_t o = (size_t)(bn + nl) * J.Kpad + bk + cl;
        J.o0[o] = a; J.o1[o] = b;
    }
}

__global__ __launch_bounds__(256)
void conv_wref_t(const float* __restrict__ Wref,
                 __nv_bfloat16* __restrict__ o0, __nv_bfloat16* __restrict__ o1)
{
    __shared__ float s[64][33];
    const int bc = blockIdx.x * 64;
    const int bn = blockIdx.y * 32;
    const int tx = threadIdx.x & 31;
    const int ty = threadIdx.x >> 5;
    const int n = bn + tx;

#pragma unroll
    for (int i = 0; i < 8; i++) {
        int cl = ty + i * 8;
        int c = bc + cl;
        float v = 0.f;
        if (n < DSE) {
            if (c < 64) {
                for (int t = 0; t < TT; t++)
                    v += Wref[(size_t)(t * DSE + SE + c) * DSE + n];
            } else if (c < KREAL) {
                int cc = c - 64;
                int t = cc / SE, kk = cc - t * SE;
                v = Wref[(size_t)(t * DSE + kk) * DSE + n];
            }
        }
        s[cl][tx] = v;
    }
    __syncthreads();

    const int cl = threadIdx.x & 63;
    const int nb = threadIdx.x >> 6;
#pragma unroll
    for (int i = 0; i < 8; i++) {
        int nl = nb + i * 4;
        float v = s[cl][nl];
        __nv_bfloat16 a, b; split2(v, a, b);
        size_t o = (size_t)(bn + nl) * KCOMB + bc + cl;
        o0[o] = a; o1[o] = b;
    }
}

// ---------------- split-K reduce ----------------
__global__ __launch_bounds__(256)
void enc_reduce(const float* __restrict__ p0, const float* __restrict__ p1,
                const float* __restrict__ p2,
                __nv_bfloat16* __restrict__ o0, __nv_bfloat16* __restrict__ o1)
{
    size_t g = ((size_t)blockIdx.x * 256 + threadIdx.x) * 8;
    if (g >= (size_t)BB * DSEP) return;
    ushort h0[8], h1[8];
#pragma unroll
    for (int i = 0; i < 8; i += 4) {
        float4 a = *(const float4*)(p0 + g + i);
        float4 b = *(const float4*)(p1 + g + i);
        float4 c = *(const float4*)(p2 + g + i);
        float s[4] = {a.x + b.x + c.x, a.y + b.y + c.y, a.z + b.z + c.z, a.w + b.w + c.w};
#pragma unroll
        for (int j = 0; j < 4; j++) {
            __nv_bfloat16 x, y; split2(s[j], x, y);
            h0[i + j] = __bfloat16_as_ushort(x);
            h1[i + j] = __bfloat16_as_ushort(y);
        }
    }
    *(uint4*)(o0 + g) = *(uint4*)h0;
    *(uint4*)(o1 + g) = *(uint4*)h1;
}

// ---------------- fused prep ----------------
__global__ __launch_bounds__(128)
void prep_mega(const float* __restrict__ fW3, const float* __restrict__ cW3,
               const float* __restrict__ Wl, const float* __restrict__ Ws, const float* __restrict__ Wm,
               const float* __restrict__ cWl, const float* __restrict__ cWs, const float* __restrict__ cWm,
               const float* __restrict__ fb3, const float* __restrict__ cb3,
               const float* __restrict__ gW1, const float* __restrict__ gb1,
               const float* __restrict__ gW2, const float* __restrict__ gb2,
               __nv_bfloat16* __restrict__ f3w0, __nv_bfloat16* __restrict__ f3w1,
               __nv_bfloat16* __restrict__ c3w0, __nv_bfloat16* __restrict__ c3w1,
               float* __restrict__ fbias, float* __restrict__ cbias, float* __restrict__ gc)
{
    const int bid = blockIdx.x;
    const int t = threadIdx.x;
    if (bid < 496) {
        const int j = bid % 62, kb = bid / 62;
        __shared__ float wh[DSE];
        for (int d = t; d < DSE; d += 128) {
            float w;
            if (j < 25)      w = Wl[d * G5 + j];
            else if (j < 37) w = Ws[d * SS + (j - 25)];
            else             w = Wm[d * G5 + (j - 37)];
            wh[d] = w;
        }
        __syncthreads();
        const int k = kb * 128 + t;
        float acc = 0.f;
        for (int d = 0; d < DSE; d++) acc = fmaf(__ldg(&fW3[(size_t)k * DSE + d]), wh[d], acc);
        __nv_bfloat16 a, b; split2(acc, a, b);
        size_t o = (size_t)(DSE + j) * HH + k;
        f3w0[o] = a; f3w1[o] = b;
        if (k == 0) {
            float bb = 0.f;
            for (int d = 0; d < DSE; d++) bb = fmaf(__ldg(&fb3[d]), wh[d], bb);
            fbias[DSE + j] = bb;
        }
    } else if (bid < 992) {
        const int j = (bid - 496) % 62, kb = (bid - 496) / 62;
        __shared__ float whc[CC];
        if (t < CC) {
            float w;
            if (j < 25)      w = cWl[t * G5 + j];
            else if (j < 37) w = cWs[t * SS + (j - 25)];
            else             w = cWm[t * G5 + (j - 37)];
            whc[t] = w;
        }
        __syncthreads();
        const int k = kb * 128 + t;
        float acc = 0.f;
        for (int d = 0; d < CC; d++) acc = fmaf(__ldg(&cW3[(size_t)k * CC + d]), whc[d], acc);
        __nv_bfloat16 a, b; split2(acc, a, b);
        size_t o = (size_t)(CC + j) * HH + k;
        c3w0[o] = a; c3w1[o] = b;
        if (k == 0) {
            float bb = 0.f;
            for (int d = 0; d < CC; d++) bb = fmaf(__ldg(&cb3[d]), whc[d], bb);
            cbias[CC + j] = bb;
        }
    } else if (bid < 994) {
        int d = (bid - 992) * 128 + t;
        if (d >= DSE) return;
        float c0 = 0.f, c1 = 0.f, c2 = 0.f, c3 = 0.f, c4 = 0.f;
        for (int h = 0; h < DSE; h++) {
            float a = gW1[d * DSE + h], b = gb1[d * DSE + h], w = gW2[d * DSE + h];
            float b2 = b * b, a2 = a * a;
            c0 += w * (0.69314718056f + 0.5f * b + 0.125f * b2 - (1.f/192.f) * b2 * b2);
            c1 += w * (0.5f * a + 0.25f * a * b - (4.f/192.f) * a * b * b2);
            c2 += w * (0.125f * a2 - (6.f/192.f) * a2 * b2);
            c3 += w * (-(4.f/192.f) * a2 * a * b);
            c4 += w * (-(1.f/192.f) * a2 * a2);
        }
        gc[d * 5 + 0] = c0 + gb2[d];
        gc[d * 5 + 1] = c1;
        gc[d * 5 + 2] = c2;
        gc[d * 5 + 3] = c3;
        gc[d * 5 + 4] = c4;
    } else {
        int x = (bid - 994) * 128 + t;
        if (x < NF3) {
            if (x < DSE) fbias[x] = fb3[x];
            else if (x >= DSE + 62) fbias[x] = 0.f;
        }
        if (x < NC3) {
            if (x < CC) cbias[x] = cb3[x];
            else if (x >= CC + 62) cbias[x] = 0.f;
        }
    }
}

// ---------------- tcgen05 GEMM: 6-stage K=16 pipeline, specialized consumer warp ----------------
struct GJob {
    const __nv_bfloat16 *A0, *A1, *B0, *B1;
    const float* bias;
    float* Cf;
    __nv_bfloat16 *C0, *C1;
    const float* gc; float* Cg;
    int lda, ldb, ldc, Nreal, Ng, kt0, ktn, epi, outm, gx;
};

#define TN 128
#define NTHR 288
#define NSTG 6
#define PSLOT 4096u                       // one plane tile: 128 rows x 32B
#define GSTRIDE (4u * PSLOT)              // A0 A1 B0 B1 = 16KB
#define GCTRL (6u * GSTRIDE)              // 98304
// control: consume mbars @ +0..+40 ; full mbars @ +48..+88 ; tmem ptr @ +96
#define SMB (GCTRL + 128u)

__global__ __launch_bounds__(NTHR, 2)
void tc_gemm_multi(GJob j0, GJob j1, GJob j2, GJob j3, int n0, int n1, int n2)
{
    extern __shared__ char smem[];
    const uint32_t sbase = smem_u32(smem);
    const int tid = threadIdx.x, wid = tid >> 5, lid = tid & 31;

    GJob J; int bid;
    if ((int)blockIdx.x < n0)      { J = j0; bid = blockIdx.x; }
    else if ((int)blockIdx.x < n1) { J = j1; bid = blockIdx.x - n0; }
    else if ((int)blockIdx.x < n2) { J = j2; bid = blockIdx.x - n1; }
    else                           { J = j3; bid = blockIdx.x - n2; }
    const int bm = (bid / J.gx) * 128;
    const int bn = (bid % J.gx) * TN;
    const int ktiles = J.ktn;

#if TC_PATH
    constexpr uint32_t IDESC = (1u << 4) | (1u << 7) | (1u << 10) | ((TN / 8) << 17) | (8u << 24);

    if (tid == 0) {
#pragma unroll
        for (int s = 0; s < NSTG; s++) {
            mbar_init(sbase + GCTRL + 8 * s, 1);          // consume[s]
            mbar_init(sbase + GCTRL + 48 + 8 * s, 256);   // full[s]
        }
    }
    if (wid == 0) {
        tmem_alloc(sbase + GCTRL + 96, TN);
        tmem_relinquish();   // release permit so the co-resident CTA can alloc
    }
    __syncthreads();
    uint32_t tmem;
    asm volatile("ld.shared.b32 %0, [%1];" : "=r"(tmem) : "r"(sbase + GCTRL + 96));

    if (tid < 256) {
        // ---------- producers: 1 cp.async per plane per chunk ----------
        const int r = tid >> 1, c16 = tid & 1;
        const uint32_t sw = SW32((r << 5) + (c16 << 4));
        const size_t aoff0 = (size_t)(bm + r) * J.lda + (c16 << 3);
        const size_t boff0 = (size_t)(bn + r) * J.ldb + (c16 << 3);
        int phc[NSTG] = {0, 0, 0, 0, 0, 0};
        for (int it = 0; it < ktiles; ++it) {
            const int b = it % NSTG;
            if (it >= NSTG) { mbar_wait(sbase + GCTRL + 8 * b, phc[b]); phc[b] ^= 1; }
            const int k0 = (J.kt0 + it) << 4;
            const uint32_t bo = sbase + (uint32_t)b * GSTRIDE;
            cp_async16(bo + sw,              J.A0 + aoff0 + k0);
            cp_async16(bo + PSLOT + sw,      J.A1 + aoff0 + k0);
            cp_async16(bo + 2u * PSLOT + sw, J.B0 + boff0 + k0);
            cp_async16(bo + 3u * PSLOT + sw, J.B1 + boff0 + k0);
            cp_async_mbar_arrive_noinc(sbase + GCTRL + 48 + 8 * b);
        }
    } else if (tid == 256) {
        // ---------- consumer: dedicated MMA thread ----------
        int phf[NSTG] = {0, 0, 0, 0, 0, 0};
        for (int it = 0; it < ktiles; ++it) {
            const int b = it % NSTG;
            mbar_wait(sbase + GCTRL + 48 + 8 * b, phf[b]); phf[b] ^= 1;
            fence_proxy_async_cta();
            const uint32_t bo = sbase + (uint32_t)b * GSTRIDE;
#pragma unroll
            for (int s3 = 0; s3 < 3; s3++) {
                const int pa = (s3 == 2) ? 1 : 0;
                const int pb = (s3 == 1) ? 1 : 0;
                uint64_t ad = smem_desc_sw32(bo + (uint32_t)pa * PSLOT);
                uint64_t bd = smem_desc_sw32(bo + (2u + (uint32_t)pb) * PSLOT);
                mma_f16_ss(tmem, ad, bd, IDESC, !(it == 0 && s3 == 0));
            }
            tc_commit(sbase + GCTRL + 8u * (uint32_t)b);
        }
    }
    __syncthreads();
    {
        // wait for the last commit: consume[(kt-1)%6] has had floor((kt-1)/6)+1 arrivals
        const int bstar = (ktiles - 1) % NSTG;
        const int nstar = (ktiles - 1) / NSTG + 1;
        mbar_wait(sbase + GCTRL + 8 * bstar, (nstar - 1) & 1);
    }
    tc_fence_after();
    __syncthreads();

    float* stage = (float*)smem;
    if (wid < 4) {
        const int mloc = wid * 32 + lid;
#pragma unroll
        for (int c0 = 0; c0 < TN; c0 += 32) {
            uint32_t r[32];
            TC_LD_X32(r, tmem + c0);
            TC_WAIT_LD();
#pragma unroll
            for (int j = 0; j < 32; j++) {
                int n = bn + c0 + j;
                float v = __uint_as_float(r[j]);
                if (J.epi >= 1) v += __ldg(&J.bias[n]);
                if (J.epi == 2) v = softplusf(v);
                stage[mloc * (TN + 1) + c0 + j] = v;
            }
        }
    }
    __syncthreads();

    for (int i = tid; i < 128 * TN; i += NTHR) {
        int ml = i / TN, n = i - ml * TN;
        float v = stage[ml * (TN + 1) + n];
        int gn = bn + n;
        if (J.outm == 1) {
            size_t o = (size_t)(bm + ml) * J.ldc + gn;
            __nv_bfloat16 h0, h1; split2(v, h0, h1);
            J.C0[o] = h0; J.C1[o] = h1;
        } else if (gn < J.Nreal) {
            size_t o = (size_t)(bm + ml) * J.ldc + gn;
            J.Cf[o] = v;
            if (gn < J.Ng) {
                const float* c = J.gc + gn * 5;
                float p = c[0] + v * (c[1] + v * (c[2] + v * (c[3] + v * c[4])));
                J.Cg[o] = 1.f / (1.f + __expf(-p));
            }
        }
    }
    __syncthreads();
    if (wid == 0) tmem_dealloc(tmem, TN);

#else  // ---------- SIMT fallback (generic PTX pass; never runs on sm_103a) ----------
    (void)smem;
    for (int i = tid; i < 128 * TN; i += NTHR) {
        int ml = i / TN, n = i - ml * TN;
        int m = bm + ml, gn = bn + n;
        float acc = 0.f;
        for (int kt = 0; kt < J.ktn; kt++) {
            int kb = (J.kt0 + kt) << 4;
            for (int k = kb; k < kb + 16; k++) {
                float a = __bfloat162float(J.A0[(size_t)m * J.lda + k]) +
                          __bfloat162float(J.A1[(size_t)m * J.lda + k]);
                float b = __bfloat162float(J.B0[(size_t)gn * J.ldb + k]) +
                          __bfloat162float(J.B1[(size_t)gn * J.ldb + k]);
                acc = fmaf(a, b, acc);
            }
        }
        if (J.epi >= 1) acc += J.bias[gn];
        if (J.epi == 2) acc = softplusf(acc);
        if (J.outm == 1) {
            size_t o = (size_t)m * J.ldc + gn;
            __nv_bfloat16 h0, h1; split2(acc, h0, h1);
            J.C0[o] = h0; J.C1[o] = h1;
        } else if (gn < J.Nreal) {
            size_t o = (size_t)m * J.ldc + gn;
            J.Cf[o] = acc;
            if (gn < J.Ng) {
                const float* c = J.gc + gn * 5;
                float p = c[0] + acc * (c[1] + acc * (c[2] + acc * (c[3] + acc * c[4])));
                J.Cg[o] = 1.f / (1.f + __expf(-p));
            }
        }
    }
#endif
}

// ---------------- final assembly ----------------
__global__ __launch_bounds__(128)
void heads_asm(const float* __restrict__ fout, const float* __restrict__ cout,
               const float* __restrict__ gout, float* __restrict__ out)
{
    const int b = blockIdx.x;
    const int t = threadIdx.x;
    __shared__ float fr[62], cr[62], sctx[CC];
    __shared__ float mx[2], lse[2];

    if (t < 62)       fr[t] = fout[(size_t)b * NF3 + DSE + t];
    else if (t < 124) cr[t - 62] = cout[(size_t)b * NC3 + CC + (t - 62)];
    if (t < CC) sctx[t] = cout[(size_t)b * NC3 + t];
    __syncthreads();

    if (t == 0) {
        float m = -1e30f;
        for (int i = 25; i < 37; i++) m = fmaxf(m, fr[i]);
        float s = 0.f;
        for (int i = 25; i < 37; i++) s += __expf(fr[i] - m);
        mx[0] = m; lse[0] = __logf(s);
    } else if (t == 32) {
        float m = -1e30f;
        for (int i = 25; i < 37; i++) m = fmaxf(m, cr[i]);
        float s = 0.f;
        for (int i = 25; i < 37; i++) s += __expf(cr[i] - m);
        mx[1] = m; lse[1] = __logf(s);
    }
    __syncthreads();

    float* o = out + (size_t)b * OUTW;
    const float* gr = gout + (size_t)b * NF3;
    for (int i = t; i < OUTW; i += 128) {
        float v;
        if (i < 25)        v = fr[i];
        else if (i < 37)   v = fr[i] - mx[0] - lse[0];
        else if (i < 62)   v = fr[i];
        else if (i < 289)  v = gr[i - 62];
        else if (i < 314)  v = cr[i - 289];
        else if (i < 326)  v = cr[25 + (i - 314)] - mx[1] - lse[1];
        else if (i < 351)  v = cr[37 + (i - 326)];
        else               v = sctx[i - 351];
        o[i] = v;
    }
}

// ---------------- launch ----------------
#define GETP2(name) \
    __nv_bfloat16 *name##0, *name##1; \
    cudaGetSymbolAddress((void**)&name##0, name##_0); \
    cudaGetSymbolAddress((void**)&name##1, name##_1);

extern "C" void kernel_launch(void* const* d_in, const int* in_sizes, int n_in,
                              void* d_out, int out_size)
{
    const float* se    = (const float*)d_in[0];
    const float* pz    = (const float*)d_in[1];
    const float* Wref  = (const float*)d_in[2];
    const float* fW1   = (const float*)d_in[3];
    const float* fb1   = (const float*)d_in[4];
    const float* fW2   = (const float*)d_in[5];
    const float* fb2   = (const float*)d_in[6];
    const float* fW3   = (const float*)d_in[7];
    const float* fb3   = (const float*)d_in[8];
    const float* gW1   = (const float*)d_in[9];
    const float* gb1   = (const float*)d_in[10];
    const float* gW2   = (const float*)d_in[11];
    const float* gb2   = (const float*)d_in[12];
    const float* Wland = (const float*)d_in[13];
    const float* Wshot = (const float*)d_in[14];
    const float* Wmove = (const float*)d_in[15];
    const float* cW1   = (const float*)d_in[16];
    const float* cb1   = (const float*)d_in[17];
    const float* cW2   = (const float*)d_in[18];
    const float* cb2   = (const float*)d_in[19];
    const float* cW3   = (const float*)d_in[20];
    const float* cb3   = (const float*)d_in[21];
    const float* cWl   = (const float*)d_in[22];
    const float* cWs   = (const float*)d_in[23];
    const float* cWm   = (const float*)d_in[24];
    float* out = (float*)d_out;

    GETP2(g_Ac)  GETP2(g_ch1) GETP2(g_ch2) GETP2(g_fin) GETP2(g_fh1) GETP2(g_fh2)
    GETP2(g_Br)  GETP2(g_c1w) GETP2(g_c2w) GETP2(g_c3w) GETP2(g_f1w) GETP2(g_f2w) GETP2(g_f3w)

    float *fout, *cout, *gout, *gc, *fbias, *cbias, *ep0, *ep1, *ep2;
    cudaGetSymbolAddress((void**)&fout,  d_fout);
    cudaGetSymbolAddress((void**)&cout,  d_cout);
    cudaGetSymbolAddress((void**)&gout,  d_gout);
    cudaGetSymbolAddress((void**)&gc,    d_gc);
    cudaGetSymbolAddress((void**)&fbias, d_fbias);
    cudaGetSymbolAddress((void**)&cbias, d_cbias);
    cudaGetSymbolAddress((void**)&ep0,   d_ep0);
    cudaGetSymbolAddress((void**)&ep1,   d_ep1);
    cudaGetSymbolAddress((void**)&ep2,   d_ep2);

    cudaFuncSetAttribute(tc_gemm_multi, cudaFuncAttributeMaxDynamicSharedMemorySize, SMB);

    const int MT = BB / 128;   // 32

    // 0: activations
    {
        size_t n = (size_t)BB * (KCOMB / 8);
        conv_act_kernel<<<(unsigned)((n + 255) / 256), 256>>>(pz, se, g_Ac0, g_Ac1);
    }
    // 1: W_ref reorder
    conv_wref_t<<<dim3(KCOMB / 64, DSEP / 32), 256>>>(Wref, g_Br0, g_Br1);
    // 2: cW1 conversion
    conv_w_t<<<dim3(1, HH / 32), 256>>>(cW1, g_c1w0, g_c1w1, 64, HH, 64);

    // 3: encoder split-K x3 || ch1   (K chunks of 16: 364 total = 122+121+121)
    {
        GJob e0 = {g_Ac0, g_Ac1, g_Br0, g_Br1, nullptr, ep0, nullptr, nullptr,
                   nullptr, nullptr, KCOMB, KCOMB, DSEP, DSEP, 0, 0, 122, 0, 0, 2};
        GJob e1 = e0; e1.Cf = ep1; e1.kt0 = 122; e1.ktn = 121;
        GJob e2 = e0; e2.Cf = ep2; e2.kt0 = 243; e2.ktn = 121;
        GJob ch1 = {g_Ac0, g_Ac1, g_c1w0, g_c1w1, cb1, nullptr, g_ch10, g_ch11,
                    nullptr, nullptr, KCOMB, 64, HH, HH, 0, 0, 4, 2, 1, 8};
        tc_gemm_multi<<<64 + 64 + 64 + 8 * MT, NTHR, SMB>>>(e0, e1, e2, ch1, 64, 128, 192);
    }

    // 4: fused conversions
    {
        CJob a = {cW2, g_c2w0, g_c2w1, HH, HH, HH, 16, 512};
        CJob b = {cW3, g_c3w0, g_c3w1, HH, CC, HH, 16, 512 + 64};
        CJob c = {fW1, g_f1w0, g_f1w1, DSE, HH, DSEP, 4, 512 + 64 + 128};
        CJob d = {fW2, g_f2w0, g_f2w1, HH, HH, HH, 16, 512 + 64 + 128 + 512};
        CJob e = {fW3, g_f3w0, g_f3w1, HH, DSE, HH, 16, 512 + 64 + 128 + 512 + 192};
        conv_multi<<<512 + 64 + 128 + 512 + 192, 256>>>(a, b, c, d, e);
    }
    // 5: split-K reduce
    enc_reduce<<<(BB * DSEP) / (256 * 8), 256>>>(ep0, ep1, ep2, g_fin0, g_fin1);
    // 6: prep
    prep_mega<<<998, 128>>>(fW3, cW3, Wland, Wshot, Wmove, cWl, cWs, cWm,
                            fb3, cb3, gW1, gb1, gW2, gb2,
                            g_f3w0, g_f3w1, g_c3w0, g_c3w1, fbias, cbias, gc);

    // 7: ch2 || f1
    {
        GJob ch2 = {g_ch10, g_ch11, g_c2w0, g_c2w1, cb2, nullptr, g_ch20, g_ch21,
                    nullptr, nullptr, HH, HH, HH, HH, 0, 0, 64, 2, 1, 8};
        GJob f1  = {g_fin0, g_fin1, g_f1w0, g_f1w1, fb1, nullptr, g_fh10, g_fh11,
                    nullptr, nullptr, DSEP, DSEP, HH, HH, 0, 0, 16, 2, 1, 8};
        tc_gemm_multi<<<8 * MT + 8 * MT, NTHR, SMB>>>(ch2, f1, ch2, f1, 8 * MT, 16 * MT, 16 * MT);
    }
    // 8: f2 || c3ext
    {
        GJob f2 = {g_fh10, g_fh11, g_f2w0, g_f2w1, fb2, nullptr, g_fh20, g_fh21,
                   nullptr, nullptr, HH, HH, HH, HH, 0, 0, 64, 2, 1, 8};
        GJob c3 = {g_ch20, g_ch21, g_c3w0, g_c3w1, cbias, cout, nullptr, nullptr,
                   nullptr, nullptr, HH, HH, NC3, CC + 62, 0, 0, 64, 1, 0, 1};
        tc_gemm_multi<<<8 * MT + 1 * MT, NTHR, SMB>>>(f2, c3, f2, c3, 8 * MT, 9 * MT, 9 * MT);
    }
    // 9: f3ext
    {
        GJob f3 = {g_fh20, g_fh21, g_f3w0, g_f3w1, fbias, fout, nullptr, nullptr,
                   gc, gout, HH, HH, NF3, DSE + 62, DSE, 0, 64, 1, 0, 3};
        tc_gemm_multi<<<3 * MT, NTHR, SMB>>>(f3, f3, f3, f3, 3 * MT, 3 * MT, 3 * MT);
    }
    // 10: assembly
    heads_asm<<<BB, 128>>>(fout, cout, gout, out);
}

// round 16
// speedup vs baseline: 1.3286x; 1.3286x over previous
#include <cuda_runtime.h>
#include <cuda_bf16.h>
#include <math.h>
#include <stdint.h>

// ---- arch-specific gate ----
#if defined(__CUDA_ARCH__)
#  if defined(__CUDA_ARCH_FEAT_SM103_ALL) || defined(__CUDA_ARCH_FEAT_SM101_ALL) || \
      defined(__CUDA_ARCH_FEAT_SM100_ALL) || defined(__CUDA_ARCH_SPECIFIC__) ||     \
      defined(__CUDA_ARCH_FAMILY_SPECIFIC__)
#    define TC_PATH 1
#  else
#    define TC_PATH 0
#  endif
#else
#  define TC_PATH 0
#endif

// ---------------- problem dims ----------------
#define BB   4096
#define TT   35
#define DSE  227
#define SE   163
#define CC   64
#define HH   1024
#define G5   25
#define SS   12
#define OUTW 415

#define KREAL (64 + TT*SE)   // 5769
#define KCOMB 5824
#define DSEP  256
#define NF3   384
#define NC3   128

// ---------------- scratch ----------------
#define PLANES2(name, sz) \
    __device__ __align__(16) __nv_bfloat16 name##_0[sz]; \
    __device__ __align__(16) __nv_bfloat16 name##_1[sz];

PLANES2(g_Ac,  BB * KCOMB)
PLANES2(g_ch1, BB * HH)
PLANES2(g_ch2, BB * HH)
PLANES2(g_fin, BB * DSEP)
PLANES2(g_fh1, BB * HH)
PLANES2(g_fh2, BB * HH)
PLANES2(g_Br,  DSEP * KCOMB)
PLANES2(g_c1w, HH * 64)
PLANES2(g_c2w, HH * HH)
PLANES2(g_c3w, NC3 * HH)
PLANES2(g_f1w, HH * DSEP)
PLANES2(g_f2w, HH * HH)
PLANES2(g_f3w, NF3 * HH)

__device__ __align__(16) float d_ep0[BB * DSEP];
__device__ __align__(16) float d_ep1[BB * DSEP];
__device__ __align__(16) float d_ep2[BB * DSEP];
__device__ float d_fout[BB * NF3];
__device__ float d_cout[BB * NC3];
__device__ float d_gout[BB * NF3];
__device__ float d_gc[DSE * 5];
__device__ float d_fbias[NF3];
__device__ float d_cbias[NC3];

// ---------------- math helpers ----------------
__device__ __forceinline__ float softplusf(float x) {
    return fmaxf(x, 0.f) + __logf(1.f + __expf(-fabsf(x)));
}
__device__ __forceinline__ void split2(float v, __nv_bfloat16& p0, __nv_bfloat16& p1) {
    p0 = __float2bfloat16(v);
    p1 = __float2bfloat16(v - __bfloat162float(p0));
}

// ---------------- PTX helpers ----------------
__device__ __forceinline__ uint32_t smem_u32(const void* p) {
    uint32_t a;
    asm("{ .reg .u64 t; cvta.to.shared.u64 t, %1; cvt.u32.u64 %0, t; }" : "=r"(a) : "l"(p));
    return a;
}
__device__ __forceinline__ uint32_t elect_one() {
    uint32_t pred;
    asm volatile("{\n\t.reg .pred p;\n\telect.sync _|p, 0xFFFFFFFF;\n\tselp.b32 %0, 1, 0, p;\n\t}" : "=r"(pred));
    return pred;
}
__device__ __forceinline__ void mbar_init(uint32_t addr, uint32_t cnt) {
    asm volatile("mbarrier.init.shared.b64 [%0], %1;" :: "r"(addr), "r"(cnt) : "memory");
}
__device__ __forceinline__ void mbar_wait(uint32_t addr, uint32_t parity) {
    uint32_t done;
    asm volatile("{\n\t.reg .pred p;\n\t"
        "mbarrier.try_wait.parity.acquire.cta.shared::cta.b64 p, [%1], %2;\n\t"
        "selp.b32 %0, 1, 0, p;\n\t}"
        : "=r"(done) : "r"(addr), "r"(parity) : "memory");
    while (!done) {
        asm volatile("{\n\t.reg .pred p;\n\t"
            "mbarrier.try_wait.parity.acquire.cta.shared::cta.b64 p, [%1], %2, 0x989680;\n\t"
            "selp.b32 %0, 1, 0, p;\n\t}"
            : "=r"(done) : "r"(addr), "r"(parity) : "memory");
    }
}
__device__ __forceinline__ void fence_proxy_async_cta() {
    asm volatile("fence.proxy.async.shared::cta;" ::: "memory");
}
__device__ __forceinline__ void cp_async16(uint32_t dst, const void* src) {
    asm volatile("cp.async.cg.shared.global [%0], [%1], 16;" :: "r"(dst), "l"(src) : "memory");
}
__device__ __forceinline__ void cp_commit() {
    asm volatile("cp.async.commit_group;" ::: "memory");
}
template<int N>
__device__ __forceinline__ void cp_wait() {
    asm volatile("cp.async.wait_group %0;" :: "n"(N) : "memory");
}

#if TC_PATH
__device__ __forceinline__ void tmem_alloc(uint32_t smem_dst, uint32_t ncols) {
    asm volatile("tcgen05.alloc.cta_group::1.sync.aligned.shared::cta.b32 [%0], %1;"
                 :: "r"(smem_dst), "r"(ncols) : "memory");
}
__device__ __forceinline__ void tmem_dealloc(uint32_t tmem, uint32_t ncols) {
    asm volatile("tcgen05.dealloc.cta_group::1.sync.aligned.b32 %0, %1;" :: "r"(tmem), "r"(ncols));
}
__device__ __forceinline__ void tmem_relinquish() {
    asm volatile("tcgen05.relinquish_alloc_permit.cta_group::1.sync.aligned;");
}
__device__ __forceinline__ void tc_commit(uint32_t mbar) {
    asm volatile("tcgen05.commit.cta_group::1.mbarrier::arrive::one.shared::cluster.b64 [%0];"
                 :: "r"(mbar) : "memory");
}
__device__ __forceinline__ void tc_fence_after() {
    asm volatile("tcgen05.fence::after_thread_sync;" ::: "memory");
}
__device__ __forceinline__ void mma_f16_ss(uint32_t d, uint64_t ad, uint64_t bd,
                                           uint32_t idesc, int acc) {
    asm volatile("{\n\t.reg .pred p;\n\tsetp.ne.u32 p, %5, 0;\n\t"
        "tcgen05.mma.cta_group::1.kind::f16 [%0], %1, %2, %3, {%4, %4, %4, %4}, p;\n\t}"
        :: "r"(d), "l"(ad), "l"(bd), "r"(idesc), "r"(0u), "r"((uint32_t)acc) : "memory");
}
#define TC_LD_X32(r, addr) \
    asm volatile("tcgen05.ld.sync.aligned.32x32b.x32.b32 " \
        "{%0, %1, %2, %3, %4, %5, %6, %7, %8, %9, %10, %11, %12, %13, %14, %15, " \
        " %16, %17, %18, %19, %20, %21, %22, %23, %24, %25, %26, %27, %28, %29, %30, %31}, [%32];" \
        : "=r"((r)[0]),  "=r"((r)[1]),  "=r"((r)[2]),  "=r"((r)[3]), \
          "=r"((r)[4]),  "=r"((r)[5]),  "=r"((r)[6]),  "=r"((r)[7]), \
          "=r"((r)[8]),  "=r"((r)[9]),  "=r"((r)[10]), "=r"((r)[11]), \
          "=r"((r)[12]), "=r"((r)[13]), "=r"((r)[14]), "=r"((r)[15]), \
          "=r"((r)[16]), "=r"((r)[17]), "=r"((r)[18]), "=r"((r)[19]), \
          "=r"((r)[20]), "=r"((r)[21]), "=r"((r)[22]), "=r"((r)[23]), \
          "=r"((r)[24]), "=r"((r)[25]), "=r"((r)[26]), "=r"((r)[27]), \
          "=r"((r)[28]), "=r"((r)[29]), "=r"((r)[30]), "=r"((r)[31]) \
        : "r"(addr))
#define TC_WAIT_LD() asm volatile("tcgen05.wait::ld.sync.aligned;" ::: "memory")
#endif // TC_PATH

#define SW64(x)  ((x) ^ (((x) >> 3) & 0x30))
static __device__ __forceinline__ uint64_t smem_desc_sw64(uint32_t addr) {
    const uint64_t base = (4ull << 61) | (1ull << 46) | (32ull << 32) | (1ull << 16);
    return base | (uint64_t)((addr >> 4) & 0x3FFF);
}

// ---------------- job structs ----------------
struct GJob {
    const __nv_bfloat16 *A0, *A1, *B0, *B1;
    const float* bias;
    float* Cf;
    __nv_bfloat16 *C0, *C1;
    const float* gc; float* Cg;
    int lda, ldb, ldc, Nreal, Ng, kt0, ktn, epi, outm, gx;
};
struct CJob {
    const float* W;
    __nv_bfloat16 *o0, *o1;
    int Kreal, Nreal, Kpad, gx, end;
};
struct C5 { CJob j[5]; };

#define NCONV 1408

// conv aux region: pure-input -> disjoint-output weight transposes (no race)
__device__ void conv_region(const C5& C, int cb) {
    CJob J; int start = 0;
#pragma unroll
    for (int i = 0; i < 5; i++) {
        if (cb < C.j[i].end) { J = C.j[i]; break; }
        start = C.j[i].end;
    }
    int local = cb - start;
    const int bk = (local % J.gx) * 64;
    const int bn = (local / J.gx) * 32;

    __shared__ float s[64][33];
    const int tx = threadIdx.x & 31;
    const int ty = threadIdx.x >> 5;
#pragma unroll
    for (int i = 0; i < 8; i++) {
        int cl = ty + i * 8;
        int k = bk + cl, n = bn + tx;
        float v = (k < J.Kreal && n < J.Nreal) ? J.W[(size_t)k * J.Nreal + n] : 0.f;
        s[cl][tx] = v;
    }
    __syncthreads();
    const int cl = threadIdx.x & 63;
    const int nb = threadIdx.x >> 6;
#pragma unroll
    for (int i = 0; i < 8; i++) {
        int nl = nb + i * 4;
        float v = s[cl][nl];
        __nv_bfloat16 a, b; split2(v, a, b);
        size_t o = (size_t)(bn + nl) * J.Kpad + bk + cl;
        J.o0[o] = a; J.o1[o] = b;
    }
}

// ---------------- standalone prep (own launch: no race with conv zero-fill) ----------------
__global__ __launch_bounds__(256)
void prep_mega(const float* __restrict__ fW3, const float* __restrict__ cW3,
               const float* __restrict__ Wl, const float* __restrict__ Ws, const float* __restrict__ Wm,
               const float* __restrict__ cWl, const float* __restrict__ cWs, const float* __restrict__ cWm,
               const float* __restrict__ fb3, const float* __restrict__ cb3,
               const float* __restrict__ gW1, const float* __restrict__ gb1,
               const float* __restrict__ gW2, const float* __restrict__ gb2,
               __nv_bfloat16* __restrict__ f3w0, __nv_bfloat16* __restrict__ f3w1,
               __nv_bfloat16* __restrict__ c3w0, __nv_bfloat16* __restrict__ c3w1,
               float* __restrict__ fbias, float* __restrict__ cbias, float* __restrict__ gc)
{
    const int p = blockIdx.x;
    const int t = threadIdx.x;
    if (p < 248) {                              // headw_f
        const int j = p % 62, kb = p / 62;
        __shared__ float wh[DSE];
        for (int d = t; d < DSE; d += 256) {
            float w;
            if (j < 25)      w = Wl[d * G5 + j];
            else if (j < 37) w = Ws[d * SS + (j - 25)];
            else             w = Wm[d * G5 + (j - 37)];
            wh[d] = w;
        }
        __syncthreads();
        const int k = kb * 256 + t;
        float acc = 0.f;
        for (int d = 0; d < DSE; d++) acc = fmaf(__ldg(&fW3[(size_t)k * DSE + d]), wh[d], acc);
        __nv_bfloat16 a, b; split2(acc, a, b);
        size_t o = (size_t)(DSE + j) * HH + k;
        f3w0[o] = a; f3w1[o] = b;
        if (k == 0) {
            float bb = 0.f;
            for (int d = 0; d < DSE; d++) bb = fmaf(__ldg(&fb3[d]), wh[d], bb);
            fbias[DSE + j] = bb;
        }
    } else if (p < 496) {                       // headw_c
        const int q = p - 248;
        const int j = q % 62, kb = q / 62;
        __shared__ float whc[CC];
        if (t < CC) {
            float w;
            if (j < 25)      w = cWl[t * G5 + j];
            else if (j < 37) w = cWs[t * SS + (j - 25)];
            else             w = cWm[t * G5 + (j - 37)];
            whc[t] = w;
        }
        __syncthreads();
        const int k = kb * 256 + t;
        float acc = 0.f;
        for (int d = 0; d < CC; d++) acc = fmaf(__ldg(&cW3[(size_t)k * CC + d]), whc[d], acc);
        __nv_bfloat16 a, b; split2(acc, a, b);
        size_t o = (size_t)(CC + j) * HH + k;
        c3w0[o] = a; c3w1[o] = b;
        if (k == 0) {
            float bb = 0.f;
            for (int d = 0; d < CC; d++) bb = fmaf(__ldg(&cb3[d]), whc[d], bb);
            cbias[CC + j] = bb;
        }
    } else if (p == 496) {                      // gcoef
        int d = t;
        if (d >= DSE) return;
        float c0 = 0.f, c1 = 0.f, c2 = 0.f, c3 = 0.f, c4 = 0.f;
        for (int h = 0; h < DSE; h++) {
            float a = gW1[d * DSE + h], b = gb1[d * DSE + h], w = gW2[d * DSE + h];
            float b2 = b * b, a2 = a * a;
            c0 += w * (0.69314718056f + 0.5f * b + 0.125f * b2 - (1.f/192.f) * b2 * b2);
            c1 += w * (0.5f * a + 0.25f * a * b - (4.f/192.f) * a * b * b2);
            c2 += w * (0.125f * a2 - (6.f/192.f) * a2 * b2);
            c3 += w * (-(4.f/192.f) * a2 * a * b);
            c4 += w * (-(1.f/192.f) * a2 * a2);
        }
        gc[d * 5 + 0] = c0 + gb2[d];
        gc[d * 5 + 1] = c1;
        gc[d * 5 + 2] = c2;
        gc[d * 5 + 3] = c3;
        gc[d * 5 + 4] = c4;
    } else {                                    // bias tails (p = 497, 498)
        int x = (p - 497) * 256 + t;
        if (x < NF3) {
            if (x < DSE) fbias[x] = fb3[x];
            else if (x >= DSE + 62) fbias[x] = 0.f;
        }
        if (x < NC3) {
            if (x < CC) cbias[x] = cb3[x];
            else if (x >= CC + 62) cbias[x] = 0.f;
        }
    }
}

// ---------------- fused front kernel: conv_act || conv_wref || cW1 ----------------
#define ACT_CTAS 11648
#define WREF_CTAS 728

__global__ __launch_bounds__(256)
void front_kernel(const float* __restrict__ pz, const float* __restrict__ se,
                  const float* __restrict__ Wref, const float* __restrict__ cW1,
                  __nv_bfloat16* __restrict__ ac0, __nv_bfloat16* __restrict__ ac1,
                  __nv_bfloat16* __restrict__ br0, __nv_bfloat16* __restrict__ br1,
                  __nv_bfloat16* __restrict__ c1w0, __nv_bfloat16* __restrict__ c1w1)
{
    const int bid = blockIdx.x;
    const int t = threadIdx.x;
    if (bid < ACT_CTAS) {
        size_t g = (size_t)bid * 256 + t;
        int b = (int)(g / (KCOMB / 8));
        int c0 = (int)(g - (size_t)b * (KCOMB / 8)) * 8;
        float v[8];
#pragma unroll
        for (int i = 0; i < 8; i++) {
            int c = c0 + i;
            if (c < 64)          v[i] = __ldg(&pz[b * 64 + c]);
            else if (c < KREAL)  v[i] = __ldg(&se[(size_t)b * (TT*SE) + (c - 64)]);
            else                 v[i] = 0.f;
        }
        ushort h0[8], h1[8];
#pragma unroll
        for (int i = 0; i < 8; i++) {
            __nv_bfloat16 a, bq; split2(v[i], a, bq);
            h0[i] = __bfloat16_as_ushort(a);
            h1[i] = __bfloat16_as_ushort(bq);
        }
        size_t o = (size_t)b * KCOMB + c0;
        *(uint4*)(ac0 + o) = *(uint4*)h0;
        *(uint4*)(ac1 + o) = *(uint4*)h1;
        return;
    }
    __shared__ float s[64][33];
    const int tx = t & 31;
    const int ty = t >> 5;
    if (bid < ACT_CTAS + WREF_CTAS) {
        int local = bid - ACT_CTAS;
        const int bc = (local % (KCOMB / 64)) * 64;
        const int bn = (local / (KCOMB / 64)) * 32;
        const int n = bn + tx;
#pragma unroll
        for (int i = 0; i < 8; i++) {
            int cl = ty + i * 8;
            int c = bc + cl;
            float v = 0.f;
            if (n < DSE) {
                if (c < 64) {
                    for (int tt = 0; tt < TT; tt++)
                        v += Wref[(size_t)(tt * DSE + SE + c) * DSE + n];
                } else if (c < KREAL) {
                    int cc = c - 64;
                    int tt = cc / SE, kk = cc - tt * SE;
                    v = Wref[(size_t)(tt * DSE + kk) * DSE + n];
                }
            }
            s[cl][tx] = v;
        }
        __syncthreads();
        const int cl = t & 63;
        const int nb = t >> 6;
#pragma unroll
        for (int i = 0; i < 8; i++) {
            int nl = nb + i * 4;
            float v = s[cl][nl];
            __nv_bfloat16 a, b; split2(v, a, b);
            size_t o = (size_t)(bn + nl) * KCOMB + bc + cl;
            br0[o] = a; br1[o] = b;
        }
    } else {
        int local = bid - ACT_CTAS - WREF_CTAS;
        const int bn = local * 32;
#pragma unroll
        for (int i = 0; i < 8; i++) {
            int cl = ty + i * 8;
            int k = cl, n = bn + tx;
            float v = (k < 64) ? cW1[(size_t)k * HH + n] : 0.f;
            s[cl][tx] = v;
        }
        __syncthreads();
        const int cl = t & 63;
        const int nb = t >> 6;
#pragma unroll
        for (int i = 0; i < 8; i++) {
            int nl = nb + i * 4;
            float v = s[cl][nl];
            __nv_bfloat16 a, b; split2(v, a, b);
            size_t o = (size_t)(bn + nl) * 64 + cl;
            c1w0[o] = a; c1w1[o] = b;
        }
    }
}

// ---------------- split-K reduce ----------------
__global__ __launch_bounds__(256)
void enc_reduce(const float* __restrict__ p0, const float* __restrict__ p1,
                const float* __restrict__ p2,
                __nv_bfloat16* __restrict__ o0, __nv_bfloat16* __restrict__ o1)
{
    size_t g = ((size_t)blockIdx.x * 256 + threadIdx.x) * 8;
    if (g >= (size_t)BB * DSEP) return;
    ushort h0[8], h1[8];
#pragma unroll
    for (int i = 0; i < 8; i += 4) {
        float4 a = *(const float4*)(p0 + g + i);
        float4 b = *(const float4*)(p1 + g + i);
        float4 c = *(const float4*)(p2 + g + i);
        float s[4] = {a.x + b.x + c.x, a.y + b.y + c.y, a.z + b.z + c.z, a.w + b.w + c.w};
#pragma unroll
        for (int j = 0; j < 4; j++) {
            __nv_bfloat16 x, y; split2(s[j], x, y);
            h0[i + j] = __bfloat16_as_ushort(x);
            h1[i + j] = __bfloat16_as_ushort(y);
        }
    }
    *(uint4*)(o0 + g) = *(uint4*)h0;
    *(uint4*)(o1 + g) = *(uint4*)h1;
}

// ---------------- tcgen05 GEMM (R11 mainloop) + conv aux region ----------------
#define TN 128
#define PSLOT 8192u
#define GSTRIDE (4u * PSLOT)
#define GCTRL (3u * GSTRIDE)
#define SMB (GCTRL + 64u)

__global__ __launch_bounds__(256, 2)
void tc_gemm_multi(GJob j0, GJob j1, GJob j2, GJob j3, int n0, int n1, int n2, int n3,
                   C5 cjobs)
{
    extern __shared__ char smem[];
    const uint32_t sbase = smem_u32(smem);
    const int tid = threadIdx.x, wid = tid >> 5, lid = tid & 31;

    if ((int)blockIdx.x >= n3) {
        conv_region(cjobs, (int)blockIdx.x - n3);
        return;
    }

    GJob J; int bid;
    if ((int)blockIdx.x < n0)      { J = j0; bid = blockIdx.x; }
    else if ((int)blockIdx.x < n1) { J = j1; bid = blockIdx.x - n0; }
    else if ((int)blockIdx.x < n2) { J = j2; bid = blockIdx.x - n1; }
    else                           { J = j3; bid = blockIdx.x - n2; }
    const int bm = (bid / J.gx) * 128;
    const int bn = (bid % J.gx) * TN;
    const int ktiles = J.ktn;

#if TC_PATH
    constexpr uint32_t IDESC = (1u << 4) | (1u << 7) | (1u << 10) | ((TN / 8) << 17) | (8u << 24);

    if (tid == 0) {
        mbar_init(sbase + GCTRL, 1);
        mbar_init(sbase + GCTRL + 8, 1);
        mbar_init(sbase + GCTRL + 16, 1);
    }
    if (wid == 0) {
        tmem_alloc(sbase + GCTRL + 24, TN);
        tmem_relinquish();   // release permit so co-resident CTA can alloc
    }
    __syncthreads();
    uint32_t tmem;
    asm volatile("ld.shared.b32 %0, [%1];" : "=r"(tmem) : "r"(sbase + GCTRL + 24));

    const int r0 = tid >> 2, c16_0 = (tid & 3);
    const int r1 = (tid + 256) >> 2, c16_1 = ((tid + 256) & 3);
    const uint32_t sw0 = SW64((r0 << 6) + (c16_0 << 4));
    const uint32_t sw1 = SW64((r1 << 6) + (c16_1 << 4));

    int ph[3] = {0, 0, 0};
    for (int it = 0; it < ktiles + 2; ++it) {
        if (it < ktiles) {
            const int lb = it % 3;
            if (it >= 3) { mbar_wait(sbase + GCTRL + 8 * lb, ph[lb]); ph[lb] ^= 1; }
            const int k0 = (J.kt0 + it) << 5;
            const uint32_t bufoff = sbase + (uint32_t)lb * GSTRIDE;
            {
                const __nv_bfloat16* a0p = J.A0 + (size_t)bm * J.lda + k0;
                const __nv_bfloat16* a1p = J.A1 + (size_t)bm * J.lda + k0;
                cp_async16(bufoff + sw0,              a0p + (size_t)r0 * J.lda + (c16_0 << 3));
                cp_async16(bufoff + sw1,              a0p + (size_t)r1 * J.lda + (c16_1 << 3));
                cp_async16(bufoff + PSLOT + sw0,      a1p + (size_t)r0 * J.lda + (c16_0 << 3));
                cp_async16(bufoff + PSLOT + sw1,      a1p + (size_t)r1 * J.lda + (c16_1 << 3));
            }
            {
                const __nv_bfloat16* b0p = J.B0 + (size_t)bn * J.ldb + k0;
                const __nv_bfloat16* b1p = J.B1 + (size_t)bn * J.ldb + k0;
                cp_async16(bufoff + 2u * PSLOT + sw0, b0p + (size_t)r0 * J.ldb + (c16_0 << 3));
                cp_async16(bufoff + 2u * PSLOT + sw1, b0p + (size_t)r1 * J.ldb + (c16_1 << 3));
                cp_async16(bufoff + 3u * PSLOT + sw0, b1p + (size_t)r0 * J.ldb + (c16_0 << 3));
                cp_async16(bufoff + 3u * PSLOT + sw1, b1p + (size_t)r1 * J.ldb + (c16_1 << 3));
            }
            cp_commit();
        }
        const int mi = it - 2;
        if (mi >= 0) {
            if (it < ktiles) cp_wait<2>();
            else             cp_wait<0>();
            fence_proxy_async_cta();
            __syncthreads();
            if (wid == 0) {
                if (elect_one()) {
                    const int mb = mi % 3;
                    const uint32_t bo = sbase + (uint32_t)mb * GSTRIDE;
#pragma unroll
                    for (int s3 = 0; s3 < 3; s3++) {
                        const int pa = (s3 == 2) ? 1 : 0;
                        const int pb = (s3 == 1) ? 1 : 0;
                        uint64_t ad = smem_desc_sw64(bo + (uint32_t)pa * PSLOT);
                        uint64_t bd = smem_desc_sw64(bo + (2u + (uint32_t)pb) * PSLOT);
#pragma unroll
                        for (int ks = 0; ks < 2; ks++)
                            mma_f16_ss(tmem, ad + 2 * ks, bd + 2 * ks, IDESC,
                                       !(mi == 0 && s3 == 0 && ks == 0));
                    }
                    tc_commit(sbase + GCTRL + 8u * (uint32_t)mb);
                }
            }
        }
    }
    {
        const int bstar = (ktiles - 1) % 3;
        mbar_wait(sbase + GCTRL + 8 * bstar, ph[bstar]);
    }
    tc_fence_after();
    __syncthreads();

    float* stage = (float*)smem;
    if (wid < 4) {
        const int mloc = wid * 32 + lid;
#pragma unroll
        for (int c0 = 0; c0 < TN; c0 += 32) {
            uint32_t r[32];
            TC_LD_X32(r, tmem + c0);
            TC_WAIT_LD();
#pragma unroll
            for (int j = 0; j < 32; j++) {
                int n = bn + c0 + j;
                float v = __uint_as_float(r[j]);
                if (J.epi >= 1) v += __ldg(&J.bias[n]);
                if (J.epi == 2) v = softplusf(v);
                stage[mloc * (TN + 1) + c0 + j] = v;
            }
        }
    }
    __syncthreads();

    for (int i = tid; i < 128 * TN; i += 256) {
        int ml = i / TN, n = i - ml * TN;
        float v = stage[ml * (TN + 1) + n];
        int gn = bn + n;
        if (J.outm == 1) {
            size_t o = (size_t)(bm + ml) * J.ldc + gn;
            __nv_bfloat16 h0, h1; split2(v, h0, h1);
            J.C0[o] = h0; J.C1[o] = h1;
        } else if (gn < J.Nreal) {
            size_t o = (size_t)(bm + ml) * J.ldc + gn;
            J.Cf[o] = v;
            if (gn < J.Ng) {
                const float* c = J.gc + gn * 5;
                float p = c[0] + v * (c[1] + v * (c[2] + v * (c[3] + v * c[4])));
                J.Cg[o] = 1.f / (1.f + __expf(-p));
            }
        }
    }
    __syncthreads();
    if (wid == 0) tmem_dealloc(tmem, TN);

#else  // ---------- SIMT fallback (generic PTX pass; never runs on sm_103a) ----------
    (void)smem;
    for (int i = tid; i < 128 * TN; i += 256) {
        int ml = i / TN, n = i - ml * TN;
        int m = bm + ml, gn = bn + n;
        float acc = 0.f;
        for (int kt = 0; kt < J.ktn; kt++) {
            int kb = (J.kt0 + kt) << 5;
            for (int k = kb; k < kb + 32; k++) {
                float a = __bfloat162float(J.A0[(size_t)m * J.lda + k]) +
                          __bfloat162float(J.A1[(size_t)m * J.lda + k]);
                float b = __bfloat162float(J.B0[(size_t)gn * J.ldb + k]) +
                          __bfloat162float(J.B1[(size_t)gn * J.ldb + k]);
                acc = fmaf(a, b, acc);
            }
        }
        if (J.epi >= 1) acc += J.bias[gn];
        if (J.epi == 2) acc = softplusf(acc);
        if (J.outm == 1) {
            size_t o = (size_t)m * J.ldc + gn;
            __nv_bfloat16 h0, h1; split2(acc, h0, h1);
            J.C0[o] = h0; J.C1[o] = h1;
        } else if (gn < J.Nreal) {
            size_t o = (size_t)m * J.ldc + gn;
            J.Cf[o] = acc;
            if (gn < J.Ng) {
                const float* c = J.gc + gn * 5;
                float p = c[0] + acc * (c[1] + acc * (c[2] + acc * (c[3] + acc * c[4])));
                J.Cg[o] = 1.f / (1.f + __expf(-p));
            }
        }
    }
#endif
}

// ---------------- final assembly ----------------
__global__ __launch_bounds__(128)
void heads_asm(const float* __restrict__ fout, const float* __restrict__ cout,
               const float* __restrict__ gout, float* __restrict__ out)
{
    const int b = blockIdx.x;
    const int t = threadIdx.x;
    __shared__ float fr[62], cr[62], sctx[CC];
    __shared__ float mx[2], lse[2];

    if (t < 62)       fr[t] = fout[(size_t)b * NF3 + DSE + t];
    else if (t < 124) cr[t - 62] = cout[(size_t)b * NC3 + CC + (t - 62)];
    if (t < CC) sctx[t] = cout[(size_t)b * NC3 + t];
    __syncthreads();

    if (t == 0) {
        float m = -1e30f;
        for (int i = 25; i < 37; i++) m = fmaxf(m, fr[i]);
        float s = 0.f;
        for (int i = 25; i < 37; i++) s += __expf(fr[i] - m);
        mx[0] = m; lse[0] = __logf(s);
    } else if (t == 32) {
        float m = -1e30f;
        for (int i = 25; i < 37; i++) m = fmaxf(m, cr[i]);
        float s = 0.f;
        for (int i = 25; i < 37; i++) s += __expf(cr[i] - m);
        mx[1] = m; lse[1] = __logf(s);
    }
    __syncthreads();

    float* o = out + (size_t)b * OUTW;
    const float* gr = gout + (size_t)b * NF3;
    for (int i = t; i < OUTW; i += 128) {
        float v;
        if (i < 25)        v = fr[i];
        else if (i < 37)   v = fr[i] - mx[0] - lse[0];
        else if (i < 62)   v = fr[i];
        else if (i < 289)  v = gr[i - 62];
        else if (i < 314)  v = cr[i - 289];
        else if (i < 326)  v = cr[25 + (i - 314)] - mx[1] - lse[1];
        else if (i < 351)  v = cr[37 + (i - 326)];
        else               v = sctx[i - 351];
        o[i] = v;
    }
}

// ---------------- launch ----------------
#define GETP2(name) \
    __nv_bfloat16 *name##0, *name##1; \
    cudaGetSymbolAddress((void**)&name##0, name##_0); \
    cudaGetSymbolAddress((void**)&name##1, name##_1);

extern "C" void kernel_launch(void* const* d_in, const int* in_sizes, int n_in,
                              void* d_out, int out_size)
{
    const float* se    = (const float*)d_in[0];
    const float* pz    = (const float*)d_in[1];
    const float* Wref  = (const float*)d_in[2];
    const float* fW1   = (const float*)d_in[3];
    const float* fb1   = (const float*)d_in[4];
    const float* fW2   = (const float*)d_in[5];
    const float* fb2   = (const float*)d_in[6];
    const float* fW3   = (const float*)d_in[7];
    const float* fb3   = (const float*)d_in[8];
    const float* gW1   = (const float*)d_in[9];
    const float* gb1   = (const float*)d_in[10];
    const float* gW2   = (const float*)d_in[11];
    const float* gb2   = (const float*)d_in[12];
    const float* Wland = (const float*)d_in[13];
    const float* Wshot = (const float*)d_in[14];
    const float* Wmove = (const float*)d_in[15];
    const float* cW1   = (const float*)d_in[16];
    const float* cb1   = (const float*)d_in[17];
    const float* cW2   = (const float*)d_in[18];
    const float* cb2   = (const float*)d_in[19];
    const float* cW3   = (const float*)d_in[20];
    const float* cb3   = (const float*)d_in[21];
    const float* cWl   = (const float*)d_in[22];
    const float* cWs   = (const float*)d_in[23];
    const float* cWm   = (const float*)d_in[24];
    float* out = (float*)d_out;

    GETP2(g_Ac)  GETP2(g_ch1) GETP2(g_ch2) GETP2(g_fin) GETP2(g_fh1) GETP2(g_fh2)
    GETP2(g_Br)  GETP2(g_c1w) GETP2(g_c2w) GETP2(g_c3w) GETP2(g_f1w) GETP2(g_f2w) GETP2(g_f3w)

    float *fout, *cout, *gout, *gc, *fbias, *cbias, *ep0, *ep1, *ep2;
    cudaGetSymbolAddress((void**)&fout,  d_fout);
    cudaGetSymbolAddress((void**)&cout,  d_cout);
    cudaGetSymbolAddress((void**)&gout,  d_gout);
    cudaGetSymbolAddress((void**)&gc,    d_gc);
    cudaGetSymbolAddress((void**)&fbias, d_fbias);
    cudaGetSymbolAddress((void**)&cbias, d_cbias);
    cudaGetSymbolAddress((void**)&ep0,   d_ep0);
    cudaGetSymbolAddress((void**)&ep1,   d_ep1);
    cudaGetSymbolAddress((void**)&ep2,   d_ep2);

    cudaFuncSetAttribute(tc_gemm_multi, cudaFuncAttributeMaxDynamicSharedMemorySize, SMB);

    const int MT = BB / 128;   // 32
    C5 cz = {};

    // L0: fused front (act || wref || cW1)
    front_kernel<<<ACT_CTAS + WREF_CTAS + 32, 256>>>(
        pz, se, Wref, cW1, g_Ac0, g_Ac1, g_Br0, g_Br1, g_c1w0, g_c1w1);

    // L1: enc split-K x3 || ch1 || conv x5 (conv outputs have no reader/writer in L1)
    {
        GJob e0 = {g_Ac0, g_Ac1, g_Br0, g_Br1, nullptr, ep0, nullptr, nullptr,
                   nullptr, nullptr, KCOMB, KCOMB, DSEP, DSEP, 0, 0, 61, 0, 0, 2};
        GJob e1 = e0; e1.Cf = ep1; e1.kt0 = 61;  e1.ktn = 61;
        GJob e2 = e0; e2.Cf = ep2; e2.kt0 = 122; e2.ktn = 60;
        GJob ch1 = {g_Ac0, g_Ac1, g_c1w0, g_c1w1, cb1, nullptr, g_ch10, g_ch11,
                    nullptr, nullptr, KCOMB, 64, HH, HH, 0, 0, 2, 2, 1, 8};
        C5 cv;
        cv.j[0] = {cW2, g_c2w0, g_c2w1, HH, HH, HH, 16, 512};
        cv.j[1] = {cW3, g_c3w0, g_c3w1, HH, CC, HH, 16, 512 + 64};
        cv.j[2] = {fW1, g_f1w0, g_f1w1, DSE, HH, DSEP, 4, 512 + 64 + 128};
        cv.j[3] = {fW2, g_f2w0, g_f2w1, HH, HH, HH, 16, 512 + 64 + 128 + 512};
        cv.j[4] = {fW3, g_f3w0, g_f3w1, HH, DSE, HH, 16, 512 + 64 + 128 + 512 + 192};
        const int n3 = 64 + 64 + 64 + 8 * MT;   // 448
        tc_gemm_multi<<<n3 + NCONV, 256, SMB>>>(e0, e1, e2, ch1, 64, 128, 192, n3, cv);
    }

    // L2: split-K reduce
    enc_reduce<<<(BB * DSEP) / (256 * 8), 256>>>(ep0, ep1, ep2, g_fin0, g_fin1);

    // L2.5: prep (AFTER conv zero-fill; writes head rows, gc, bias)
    prep_mega<<<499, 256>>>(fW3, cW3, Wland, Wshot, Wmove, cWl, cWs, cWm,
                            fb3, cb3, gW1, gb1, gW2, gb2,
                            g_f3w0, g_f3w1, g_c3w0, g_c3w1, fbias, cbias, gc);

    // L3: ch2 || f1
    {
        GJob ch2 = {g_ch10, g_ch11, g_c2w0, g_c2w1, cb2, nullptr, g_ch20, g_ch21,
                    nullptr, nullptr, HH, HH, HH, HH, 0, 0, 32, 2, 1, 8};
        GJob f1  = {g_fin0, g_fin1, g_f1w0, g_f1w1, fb1, nullptr, g_fh10, g_fh11,
                    nullptr, nullptr, DSEP, DSEP, HH, HH, 0, 0, 8, 2, 1, 8};
        tc_gemm_multi<<<16 * MT, 256, SMB>>>(ch2, f1, ch2, f1, 8 * MT, 16 * MT, 16 * MT, 16 * MT, cz);
    }
    // L4: f2 || c3ext
    {
        GJob f2 = {g_fh10, g_fh11, g_f2w0, g_f2w1, fb2, nullptr, g_fh20, g_fh21,
                   nullptr, nullptr, HH, HH, HH, HH, 0, 0, 32, 2, 1, 8};
        GJob c3 = {g_ch20, g_ch21, g_c3w0, g_c3w1, cbias, cout, nullptr, nullptr,
                   nullptr, nullptr, HH, HH, NC3, CC + 62, 0, 0, 32, 1, 0, 1};
        tc_gemm_multi<<<9 * MT, 256, SMB>>>(f2, c3, f2, c3, 8 * MT, 9 * MT, 9 * MT, 9 * MT, cz);
    }
    // L5: f3ext (latent + heads + fused g-poly)
    {
        GJob f3 = {g_fh20, g_fh21, g_f3w0, g_f3w1, fbias, fout, nullptr, nullptr,
                   gc, gout, HH, HH, NF3, DSE + 62, DSE, 0, 32, 1, 0, 3};
        tc_gemm_multi<<<3 * MT, 256, SMB>>>(f3, f3, f3, f3, 3 * MT, 3 * MT, 3 * MT, 3 * MT, cz);
    }
    // L6: assembly
    heads_asm<<<BB, 128>>>(fout, cout, gout, out);
}

// round 17
// speedup vs baseline: 1.5134x; 1.1391x over previous
#include <cuda_runtime.h>
#include <cuda_bf16.h>
#include <math.h>
#include <stdint.h>

// ---- arch-specific gate ----
#if defined(__CUDA_ARCH__)
#  if defined(__CUDA_ARCH_FEAT_SM103_ALL) || defined(__CUDA_ARCH_FEAT_SM101_ALL) || \
      defined(__CUDA_ARCH_FEAT_SM100_ALL) || defined(__CUDA_ARCH_SPECIFIC__) ||     \
      defined(__CUDA_ARCH_FAMILY_SPECIFIC__)
#    define TC_PATH 1
#  else
#    define TC_PATH 0
#  endif
#else
#  define TC_PATH 0
#endif

// ---------------- problem dims ----------------
#define BB   4096
#define TT   35
#define DSE  227
#define SE   163
#define CC   64
#define HH   1024
#define G5   25
#define SS   12
#define OUTW 415

#define KREAL (64 + TT*SE)   // 5769
#define KCOMB 5824
#define DSEP  256
#define NF3   384
#define NC3   128

// ---------------- scratch ----------------
#define PLANES2(name, sz) \
    __device__ __align__(16) __nv_bfloat16 name##_0[sz]; \
    __device__ __align__(16) __nv_bfloat16 name##_1[sz];

PLANES2(g_Ac,  BB * KCOMB)
PLANES2(g_ch1, BB * HH)
PLANES2(g_ch2, BB * HH)
PLANES2(g_fin, BB * DSEP)
PLANES2(g_fh1, BB * HH)
PLANES2(g_fh2, BB * HH)
PLANES2(g_Br,  DSEP * KCOMB)
PLANES2(g_c1w, HH * 64)
PLANES2(g_c2w, HH * HH)
PLANES2(g_c3w, NC3 * HH)
PLANES2(g_f1w, HH * DSEP)
PLANES2(g_f2w, HH * HH)
PLANES2(g_f3w, NF3 * HH)

__device__ __align__(16) float d_ep0[BB * DSEP];
__device__ __align__(16) float d_ep1[BB * DSEP];
__device__ __align__(16) float d_ep2[BB * DSEP];
__device__ float d_fout[BB * NF3];
__device__ float d_cout[BB * NC3];
__device__ float d_gout[BB * NF3];
__device__ float d_gc[DSE * 5];
__device__ float d_fbias[NF3];
__device__ float d_cbias[NC3];

// ---------------- math helpers ----------------
__device__ __forceinline__ float softplusf(float x) {
    return fmaxf(x, 0.f) + __logf(1.f + __expf(-fabsf(x)));
}
__device__ __forceinline__ void split2(float v, __nv_bfloat16& p0, __nv_bfloat16& p1) {
    p0 = __float2bfloat16(v);
    p1 = __float2bfloat16(v - __bfloat162float(p0));
}

// ---------------- PTX helpers ----------------
__device__ __forceinline__ uint32_t smem_u32(const void* p) {
    uint32_t a;
    asm("{ .reg .u64 t; cvta.to.shared.u64 t, %1; cvt.u32.u64 %0, t; }" : "=r"(a) : "l"(p));
    return a;
}
__device__ __forceinline__ uint32_t elect_one() {
    uint32_t pred;
    asm volatile("{\n\t.reg .pred p;\n\telect.sync _|p, 0xFFFFFFFF;\n\tselp.b32 %0, 1, 0, p;\n\t}" : "=r"(pred));
    return pred;
}
__device__ __forceinline__ void mbar_init(uint32_t addr, uint32_t cnt) {
    asm volatile("mbarrier.init.shared.b64 [%0], %1;" :: "r"(addr), "r"(cnt) : "memory");
}
__device__ __forceinline__ void mbar_wait(uint32_t addr, uint32_t parity) {
    uint32_t done;
    asm volatile("{\n\t.reg .pred p;\n\t"
        "mbarrier.try_wait.parity.acquire.cta.shared::cta.b64 p, [%1], %2;\n\t"
        "selp.b32 %0, 1, 0, p;\n\t}"
        : "=r"(done) : "r"(addr), "r"(parity) : "memory");
    while (!done) {
        asm volatile("{\n\t.reg .pred p;\n\t"
            "mbarrier.try_wait.parity.acquire.cta.shared::cta.b64 p, [%1], %2, 0x989680;\n\t"
            "selp.b32 %0, 1, 0, p;\n\t}"
            : "=r"(done) : "r"(addr), "r"(parity) : "memory");
    }
}
__device__ __forceinline__ void fence_proxy_async_cta() {
    asm volatile("fence.proxy.async.shared::cta;" ::: "memory");
}
__device__ __forceinline__ void cp_async16(uint32_t dst, const void* src) {
    asm volatile("cp.async.cg.shared.global [%0], [%1], 16;" :: "r"(dst), "l"(src) : "memory");
}
__device__ __forceinline__ void cp_commit() {
    asm volatile("cp.async.commit_group;" ::: "memory");
}
template<int N>
__device__ __forceinline__ void cp_wait() {
    asm volatile("cp.async.wait_group %0;" :: "n"(N) : "memory");
}

#if TC_PATH
__device__ __forceinline__ void tmem_alloc(uint32_t smem_dst, uint32_t ncols) {
    asm volatile("tcgen05.alloc.cta_group::1.sync.aligned.shared::cta.b32 [%0], %1;"
                 :: "r"(smem_dst), "r"(ncols) : "memory");
}
__device__ __forceinline__ void tmem_dealloc(uint32_t tmem, uint32_t ncols) {
    asm volatile("tcgen05.dealloc.cta_group::1.sync.aligned.b32 %0, %1;" :: "r"(tmem), "r"(ncols));
}
__device__ __forceinline__ void tmem_relinquish() {
    asm volatile("tcgen05.relinquish_alloc_permit.cta_group::1.sync.aligned;");
}
__device__ __forceinline__ void tc_commit(uint32_t mbar) {
    asm volatile("tcgen05.commit.cta_group::1.mbarrier::arrive::one.shared::cluster.b64 [%0];"
                 :: "r"(mbar) : "memory");
}
__device__ __forceinline__ void tc_fence_after() {
    asm volatile("tcgen05.fence::after_thread_sync;" ::: "memory");
}
__device__ __forceinline__ void mma_f16_ss(uint32_t d, uint64_t ad, uint64_t bd,
                                           uint32_t idesc, int acc) {
    asm volatile("{\n\t.reg .pred p;\n\tsetp.ne.u32 p, %5, 0;\n\t"
        "tcgen05.mma.cta_group::1.kind::f16 [%0], %1, %2, %3, {%4, %4, %4, %4}, p;\n\t}"
        :: "r"(d), "l"(ad), "l"(bd), "r"(idesc), "r"(0u), "r"((uint32_t)acc) : "memory");
}
#define TC_LD_X32(r, addr) \
    asm volatile("tcgen05.ld.sync.aligned.32x32b.x32.b32 " \
        "{%0, %1, %2, %3, %4, %5, %6, %7, %8, %9, %10, %11, %12, %13, %14, %15, " \
        " %16, %17, %18, %19, %20, %21, %22, %23, %24, %25, %26, %27, %28, %29, %30, %31}, [%32];" \
        : "=r"((r)[0]),  "=r"((r)[1]),  "=r"((r)[2]),  "=r"((r)[3]), \
          "=r"((r)[4]),  "=r"((r)[5]),  "=r"((r)[6]),  "=r"((r)[7]), \
          "=r"((r)[8]),  "=r"((r)[9]),  "=r"((r)[10]), "=r"((r)[11]), \
          "=r"((r)[12]), "=r"((r)[13]), "=r"((r)[14]), "=r"((r)[15]), \
          "=r"((r)[16]), "=r"((r)[17]), "=r"((r)[18]), "=r"((r)[19]), \
          "=r"((r)[20]), "=r"((r)[21]), "=r"((r)[22]), "=r"((r)[23]), \
          "=r"((r)[24]), "=r"((r)[25]), "=r"((r)[26]), "=r"((r)[27]), \
          "=r"((r)[28]), "=r"((r)[29]), "=r"((r)[30]), "=r"((r)[31]) \
        : "r"(addr))
#define TC_WAIT_LD() asm volatile("tcgen05.wait::ld.sync.aligned;" ::: "memory")
#endif // TC_PATH

#define SW64(x)  ((x) ^ (((x) >> 3) & 0x30))
static __device__ __forceinline__ uint64_t smem_desc_sw64(uint32_t addr) {
    const uint64_t base = (4ull << 61) | (1ull << 46) | (32ull << 32) | (1ull << 16);
    return base | (uint64_t)((addr >> 4) & 0x3FFF);
}

// ---------------- job structs ----------------
struct GJob {
    const __nv_bfloat16 *A0, *A1, *B0, *B1;
    const float* bias;
    float* Cf;
    __nv_bfloat16 *C0, *C1;
    const float* gc; float* Cg;
    int lda, ldb, ldc, Nreal, Ng, kt0, ktn, epi, outm, gx;
};
struct CJob {
    const float* W;
    __nv_bfloat16 *o0, *o1;
    int Kreal, Nreal, Kpad, gx, end;
};
struct C5 { CJob j[5]; };

#define NCONV 1408

// conv aux region (race-free: raw-weight inputs, exclusive outputs)
__device__ void conv_region(const C5& C, int cb) {
    CJob J; int start = 0;
#pragma unroll
    for (int i = 0; i < 5; i++) {
        if (cb < C.j[i].end) { J = C.j[i]; break; }
        start = C.j[i].end;
    }
    int local = cb - start;
    const int bk = (local % J.gx) * 64;
    const int bn = (local / J.gx) * 32;

    __shared__ float s[64][33];
    const int tx = threadIdx.x & 31;
    const int ty = threadIdx.x >> 5;
#pragma unroll
    for (int i = 0; i < 8; i++) {
        int cl = ty + i * 8;
        int k = bk + cl, n = bn + tx;
        float v = (k < J.Kreal && n < J.Nreal) ? J.W[(size_t)k * J.Nreal + n] : 0.f;
        s[cl][tx] = v;
    }
    __syncthreads();
    const int cl = threadIdx.x & 63;
    const int nb = threadIdx.x >> 6;
#pragma unroll
    for (int i = 0; i < 8; i++) {
        int nl = nb + i * 4;
        float v = s[cl][nl];
        __nv_bfloat16 a, b; split2(v, a, b);
        size_t o = (size_t)(bn + nl) * J.Kpad + bk + cl;
        J.o0[o] = a; J.o1[o] = b;
    }
}

// ---------------- fused front kernel: conv_act || conv_wref || cW1 ----------------
#define ACT_CTAS 11648
#define WREF_CTAS 728

__global__ __launch_bounds__(256)
void front_kernel(const float* __restrict__ pz, const float* __restrict__ se,
                  const float* __restrict__ Wref, const float* __restrict__ cW1,
                  __nv_bfloat16* __restrict__ ac0, __nv_bfloat16* __restrict__ ac1,
                  __nv_bfloat16* __restrict__ br0, __nv_bfloat16* __restrict__ br1,
                  __nv_bfloat16* __restrict__ c1w0, __nv_bfloat16* __restrict__ c1w1)
{
    const int bid = blockIdx.x;
    const int t = threadIdx.x;
    if (bid < ACT_CTAS) {
        size_t g = (size_t)bid * 256 + t;
        int b = (int)(g / (KCOMB / 8));
        int c0 = (int)(g - (size_t)b * (KCOMB / 8)) * 8;
        float v[8];
#pragma unroll
        for (int i = 0; i < 8; i++) {
            int c = c0 + i;
            if (c < 64)          v[i] = __ldg(&pz[b * 64 + c]);
            else if (c < KREAL)  v[i] = __ldg(&se[(size_t)b * (TT*SE) + (c - 64)]);
            else                 v[i] = 0.f;
        }
        ushort h0[8], h1[8];
#pragma unroll
        for (int i = 0; i < 8; i++) {
            __nv_bfloat16 a, bq; split2(v[i], a, bq);
            h0[i] = __bfloat16_as_ushort(a);
            h1[i] = __bfloat16_as_ushort(bq);
        }
        size_t o = (size_t)b * KCOMB + c0;
        *(uint4*)(ac0 + o) = *(uint4*)h0;
        *(uint4*)(ac1 + o) = *(uint4*)h1;
        return;
    }
    __shared__ float s[64][33];
    const int tx = t & 31;
    const int ty = t >> 5;
    if (bid < ACT_CTAS + WREF_CTAS) {
        int local = bid - ACT_CTAS;
        const int bc = (local % (KCOMB / 64)) * 64;
        const int bn = (local / (KCOMB / 64)) * 32;
        const int n = bn + tx;
#pragma unroll
        for (int i = 0; i < 8; i++) {
            int cl = ty + i * 8;
            int c = bc + cl;
            float v = 0.f;
            if (n < DSE) {
                if (c < 64) {
                    for (int tt = 0; tt < TT; tt++)
                        v += Wref[(size_t)(tt * DSE + SE + c) * DSE + n];
                } else if (c < KREAL) {
                    int cc = c - 64;
                    int tt = cc / SE, kk = cc - tt * SE;
                    v = Wref[(size_t)(tt * DSE + kk) * DSE + n];
                }
            }
            s[cl][tx] = v;
        }
        __syncthreads();
        const int cl = t & 63;
        const int nb = t >> 6;
#pragma unroll
        for (int i = 0; i < 8; i++) {
            int nl = nb + i * 4;
            float v = s[cl][nl];
            __nv_bfloat16 a, b; split2(v, a, b);
            size_t o = (size_t)(bn + nl) * KCOMB + bc + cl;
            br0[o] = a; br1[o] = b;
        }
    } else {
        int local = bid - ACT_CTAS - WREF_CTAS;
        const int bn = local * 32;
#pragma unroll
        for (int i = 0; i < 8; i++) {
            int cl = ty + i * 8;
            int k = cl, n = bn + tx;
            float v = (k < 64) ? cW1[(size_t)k * HH + n] : 0.f;
            s[cl][tx] = v;
        }
        __syncthreads();
        const int cl = t & 63;
        const int nb = t >> 6;
#pragma unroll
        for (int i = 0; i < 8; i++) {
            int nl = nb + i * 4;
            float v = s[cl][nl];
            __nv_bfloat16 a, b; split2(v, a, b);
            size_t o = (size_t)(bn + nl) * 64 + cl;
            c1w0[o] = a; c1w1[o] = b;
        }
    }
}

// ---------------- mid kernel: enc_reduce || fast prep (tiled headw, parallel gcoef) ----------------
#define RED_CTAS 512
#define MID_SMEM (32 * 228 * 4 + 227 * 64 * 4)   // 87296 B

__global__ __launch_bounds__(256)
void mid_kernel(const float* __restrict__ p0, const float* __restrict__ p1,
                const float* __restrict__ p2,
                __nv_bfloat16* __restrict__ fin0, __nv_bfloat16* __restrict__ fin1,
                const float* __restrict__ fW3, const float* __restrict__ cW3,
                const float* __restrict__ Wl, const float* __restrict__ Ws,
                const float* __restrict__ Wm,
                const float* __restrict__ cWl, const float* __restrict__ cWs,
                const float* __restrict__ cWm,
                const float* __restrict__ fb3, const float* __restrict__ cb3,
                const float* __restrict__ gW1, const float* __restrict__ gb1,
                const float* __restrict__ gW2, const float* __restrict__ gb2,
                __nv_bfloat16* __restrict__ f3w0, __nv_bfloat16* __restrict__ f3w1,
                __nv_bfloat16* __restrict__ c3w0, __nv_bfloat16* __restrict__ c3w1,
                float* __restrict__ fbias, float* __restrict__ cbias,
                float* __restrict__ gc)
{
    extern __shared__ float dsm[];
    const int bid = blockIdx.x;
    const int t = threadIdx.x;

    if (bid < RED_CTAS) {
        // split-K reduce -> fin planes
        size_t g = ((size_t)bid * 256 + t) * 8;
        ushort h0[8], h1[8];
#pragma unroll
        for (int i = 0; i < 8; i += 4) {
            float4 a = *(const float4*)(p0 + g + i);
            float4 b = *(const float4*)(p1 + g + i);
            float4 c = *(const float4*)(p2 + g + i);
            float s[4] = {a.x + b.x + c.x, a.y + b.y + c.y, a.z + b.z + c.z, a.w + b.w + c.w};
#pragma unroll
            for (int j = 0; j < 4; j++) {
                __nv_bfloat16 x, y; split2(s[j], x, y);
                h0[i + j] = __bfloat16_as_ushort(x);
                h1[i + j] = __bfloat16_as_ushort(y);
            }
        }
        *(uint4*)(fin0 + g) = *(uint4*)h0;
        *(uint4*)(fin1 + g) = *(uint4*)h1;
        return;
    }
    if (bid < RED_CTAS + 32) {
        // headw_f: k-tile of 32 rows; smem tiled, 1x8 register tile per thread
        const int kt = bid - RED_CTAS, k0 = kt * 32;
        float* sA = dsm;                 // [32][228]
        float* sW = dsm + 32 * 228;      // [227][64]
        for (int idx = t; idx < 32 * DSE; idx += 256) {
            int kl = idx / DSE, d = idx - kl * DSE;
            sA[kl * 228 + d] = __ldg(&fW3[(size_t)(k0 + kl) * DSE + d]);
        }
        for (int idx = t; idx < DSE * 62; idx += 256) {
            int d = idx / 62, j = idx - d * 62;
            float w;
            if (j < 25)      w = __ldg(&Wl[d * G5 + j]);
            else if (j < 37) w = __ldg(&Ws[d * SS + (j - 25)]);
            else             w = __ldg(&Wm[d * G5 + (j - 37)]);
            sW[d * 64 + j] = w;
        }
        __syncthreads();
        const int jg = t >> 5, kl = t & 31, j0 = jg * 8;
        float acc[8] = {0, 0, 0, 0, 0, 0, 0, 0};
        for (int d = 0; d < DSE; d++) {
            float a = sA[kl * 228 + d];
            float4 b0 = *(const float4*)&sW[d * 64 + j0];
            float4 b1 = *(const float4*)&sW[d * 64 + j0 + 4];
            acc[0] = fmaf(a, b0.x, acc[0]); acc[1] = fmaf(a, b0.y, acc[1]);
            acc[2] = fmaf(a, b0.z, acc[2]); acc[3] = fmaf(a, b0.w, acc[3]);
            acc[4] = fmaf(a, b1.x, acc[4]); acc[5] = fmaf(a, b1.y, acc[5]);
            acc[6] = fmaf(a, b1.z, acc[6]); acc[7] = fmaf(a, b1.w, acc[7]);
        }
#pragma unroll
        for (int i = 0; i < 8; i++) {
            int j = j0 + i;
            if (j < 62) {
                __nv_bfloat16 a, b; split2(acc[i], a, b);
                size_t o = (size_t)(DSE + j) * HH + k0 + kl;
                f3w0[o] = a; f3w1[o] = b;
            }
        }
        if (kt == 0 && t < 62) {
            float bb = 0.f;
            for (int d = 0; d < DSE; d++) bb = fmaf(__ldg(&fb3[d]), sW[d * 64 + t], bb);
            fbias[DSE + t] = bb;
        }
        return;
    }
    if (bid < RED_CTAS + 64) {
        // headw_c: d = 64
        const int kt = bid - RED_CTAS - 32, k0 = kt * 32;
        float* sA = dsm;                 // [32][68]
        float* sW = dsm + 32 * 68;       // [64][64]
        for (int idx = t; idx < 32 * CC; idx += 256) {
            int kl = idx / CC, d = idx - kl * CC;
            sA[kl * 68 + d] = __ldg(&cW3[(size_t)(k0 + kl) * CC + d]);
        }
        for (int idx = t; idx < CC * 62; idx += 256) {
            int d = idx / 62, j = idx - d * 62;
            float w;
            if (j < 25)      w = __ldg(&cWl[d * G5 + j]);
            else if (j < 37) w = __ldg(&cWs[d * SS + (j - 25)]);
            else             w = __ldg(&cWm[d * G5 + (j - 37)]);
            sW[d * 64 + j] = w;
        }
        __syncthreads();
        const int jg = t >> 5, kl = t & 31, j0 = jg * 8;
        float acc[8] = {0, 0, 0, 0, 0, 0, 0, 0};
        for (int d = 0; d < CC; d++) {
            float a = sA[kl * 68 + d];
            float4 b0 = *(const float4*)&sW[d * 64 + j0];
            float4 b1 = *(const float4*)&sW[d * 64 + j0 + 4];
            acc[0] = fmaf(a, b0.x, acc[0]); acc[1] = fmaf(a, b0.y, acc[1]);
            acc[2] = fmaf(a, b0.z, acc[2]); acc[3] = fmaf(a, b0.w, acc[3]);
            acc[4] = fmaf(a, b1.x, acc[4]); acc[5] = fmaf(a, b1.y, acc[5]);
            acc[6] = fmaf(a, b1.z, acc[6]); acc[7] = fmaf(a, b1.w, acc[7]);
        }
#pragma unroll
        for (int i = 0; i < 8; i++) {
            int j = j0 + i;
            if (j < 62) {
                __nv_bfloat16 a, b; split2(acc[i], a, b);
                size_t o = (size_t)(CC + j) * HH + k0 + kl;
                c3w0[o] = a; c3w1[o] = b;
            }
        }
        if (kt == 0 && t < 62) {
            float bb = 0.f;
            for (int d = 0; d < CC; d++) bb = fmaf(__ldg(&cb3[d]), sW[d * 64 + t], bb);
            cbias[CC + t] = bb;
        }
        return;
    }
    if (bid < RED_CTAS + 64 + DSE) {
        // gcoef: block per d, parallel over h, 5-way tree reduce
        const int d = bid - RED_CTAS - 64;
        float c0 = 0.f, c1 = 0.f, c2 = 0.f, c3 = 0.f, c4 = 0.f;
        if (t < DSE) {
            float a = __ldg(&gW1[d * DSE + t]), b = __ldg(&gb1[d * DSE + t]);
            float w = __ldg(&gW2[d * DSE + t]);
            float b2 = b * b, a2 = a * a;
            c0 = w * (0.69314718056f + 0.5f * b + 0.125f * b2 - (1.f/192.f) * b2 * b2);
            c1 = w * (0.5f * a + 0.25f * a * b - (4.f/192.f) * a * b * b2);
            c2 = w * (0.125f * a2 - (6.f/192.f) * a2 * b2);
            c3 = w * (-(4.f/192.f) * a2 * a * b);
            c4 = w * (-(1.f/192.f) * a2 * a2);
        }
        float* red = dsm;   // [5][256]
        red[t] = c0; red[256 + t] = c1; red[512 + t] = c2;
        red[768 + t] = c3; red[1024 + t] = c4;
        __syncthreads();
        for (int s = 128; s > 0; s >>= 1) {
            if (t < s) {
#pragma unroll
                for (int i = 0; i < 5; i++)
                    red[i * 256 + t] += red[i * 256 + t + s];
            }
            __syncthreads();
        }
        if (t == 0) {
            gc[d * 5 + 0] = red[0] + __ldg(&gb2[d]);
            gc[d * 5 + 1] = red[256];
            gc[d * 5 + 2] = red[512];
            gc[d * 5 + 3] = red[768];
            gc[d * 5 + 4] = red[1024];
        }
        return;
    }
    // bias tails
    {
        int x = (bid - (RED_CTAS + 64 + DSE)) * 256 + t;
        if (x < NF3) {
            if (x < DSE) fbias[x] = __ldg(&fb3[x]);
            else if (x >= DSE + 62) fbias[x] = 0.f;
        }
        if (x < NC3) {
            if (x < CC) cbias[x] = __ldg(&cb3[x]);
            else if (x >= CC + 62) cbias[x] = 0.f;
        }
    }
}

// ---------------- tcgen05 GEMM (R11 mainloop) + conv aux region ----------------
#define TN 128
#define PSLOT 8192u
#define GSTRIDE (4u * PSLOT)
#define GCTRL (3u * GSTRIDE)
#define SMB (GCTRL + 64u)

__global__ __launch_bounds__(256, 2)
void tc_gemm_multi(GJob j0, GJob j1, GJob j2, GJob j3, int n0, int n1, int n2, int n3,
                   C5 cjobs)
{
    extern __shared__ char smem[];
    const uint32_t sbase = smem_u32(smem);
    const int tid = threadIdx.x, wid = tid >> 5, lid = tid & 31;

    if ((int)blockIdx.x >= n3) {
        conv_region(cjobs, (int)blockIdx.x - n3);
        return;
    }

    GJob J; int bid;
    if ((int)blockIdx.x < n0)      { J = j0; bid = blockIdx.x; }
    else if ((int)blockIdx.x < n1) { J = j1; bid = blockIdx.x - n0; }
    else if ((int)blockIdx.x < n2) { J = j2; bid = blockIdx.x - n1; }
    else                           { J = j3; bid = blockIdx.x - n2; }
    const int bm = (bid / J.gx) * 128;
    const int bn = (bid % J.gx) * TN;
    const int ktiles = J.ktn;

#if TC_PATH
    constexpr uint32_t IDESC = (1u << 4) | (1u << 7) | (1u << 10) | ((TN / 8) << 17) | (8u << 24);

    if (tid == 0) {
        mbar_init(sbase + GCTRL, 1);
        mbar_init(sbase + GCTRL + 8, 1);
        mbar_init(sbase + GCTRL + 16, 1);
    }
    if (wid == 0) {
        tmem_alloc(sbase + GCTRL + 24, TN);
        tmem_relinquish();   // release permit so co-resident CTA can alloc
    }
    __syncthreads();
    uint32_t tmem;
    asm volatile("ld.shared.b32 %0, [%1];" : "=r"(tmem) : "r"(sbase + GCTRL + 24));

    const int r0 = tid >> 2, c16_0 = (tid & 3);
    const int r1 = (tid + 256) >> 2, c16_1 = ((tid + 256) & 3);
    const uint32_t sw0 = SW64((r0 << 6) + (c16_0 << 4));
    const uint32_t sw1 = SW64((r1 << 6) + (c16_1 << 4));

    int ph[3] = {0, 0, 0};
    for (int it = 0; it < ktiles + 2; ++it) {
        if (it < ktiles) {
            const int lb = it % 3;
            if (it >= 3) { mbar_wait(sbase + GCTRL + 8 * lb, ph[lb]); ph[lb] ^= 1; }
            const int k0 = (J.kt0 + it) << 5;
            const uint32_t bufoff = sbase + (uint32_t)lb * GSTRIDE;
            {
                const __nv_bfloat16* a0p = J.A0 + (size_t)bm * J.lda + k0;
                const __nv_bfloat16* a1p = J.A1 + (size_t)bm * J.lda + k0;
                cp_async16(bufoff + sw0,              a0p + (size_t)r0 * J.lda + (c16_0 << 3));
                cp_async16(bufoff + sw1,              a0p + (size_t)r1 * J.lda + (c16_1 << 3));
                cp_async16(bufoff + PSLOT + sw0,      a1p + (size_t)r0 * J.lda + (c16_0 << 3));
                cp_async16(bufoff + PSLOT + sw1,      a1p + (size_t)r1 * J.lda + (c16_1 << 3));
            }
            {
                const __nv_bfloat16* b0p = J.B0 + (size_t)bn * J.ldb + k0;
                const __nv_bfloat16* b1p = J.B1 + (size_t)bn * J.ldb + k0;
                cp_async16(bufoff + 2u * PSLOT + sw0, b0p + (size_t)r0 * J.ldb + (c16_0 << 3));
                cp_async16(bufoff + 2u * PSLOT + sw1, b0p + (size_t)r1 * J.ldb + (c16_1 << 3));
                cp_async16(bufoff + 3u * PSLOT + sw0, b1p + (size_t)r0 * J.ldb + (c16_0 << 3));
                cp_async16(bufoff + 3u * PSLOT + sw1, b1p + (size_t)r1 * J.ldb + (c16_1 << 3));
            }
            cp_commit();
        }
        const int mi = it - 2;
        if (mi >= 0) {
            if (it < ktiles) cp_wait<2>();
            else             cp_wait<0>();
            fence_proxy_async_cta();
            __syncthreads();
            if (wid == 0) {
                if (elect_one()) {
                    const int mb = mi % 3;
                    const uint32_t bo = sbase + (uint32_t)mb * GSTRIDE;
#pragma unroll
                    for (int s3 = 0; s3 < 3; s3++) {
                        const int pa = (s3 == 2) ? 1 : 0;
                        const int pb = (s3 == 1) ? 1 : 0;
                        uint64_t ad = smem_desc_sw64(bo + (uint32_t)pa * PSLOT);
                        uint64_t bd = smem_desc_sw64(bo + (2u + (uint32_t)pb) * PSLOT);
#pragma unroll
                        for (int ks = 0; ks < 2; ks++)
                            mma_f16_ss(tmem, ad + 2 * ks, bd + 2 * ks, IDESC,
                                       !(mi == 0 && s3 == 0 && ks == 0));
                    }
                    tc_commit(sbase + GCTRL + 8u * (uint32_t)mb);
                }
            }
        }
    }
    {
        const int bstar = (ktiles - 1) % 3;
        mbar_wait(sbase + GCTRL + 8 * bstar, ph[bstar]);
    }
    tc_fence_after();
    __syncthreads();

    float* stage = (float*)smem;
    if (wid < 4) {
        const int mloc = wid * 32 + lid;
#pragma unroll
        for (int c0 = 0; c0 < TN; c0 += 32) {
            uint32_t r[32];
            TC_LD_X32(r, tmem + c0);
            TC_WAIT_LD();
#pragma unroll
            for (int j = 0; j < 32; j++) {
                int n = bn + c0 + j;
                float v = __uint_as_float(r[j]);
                if (J.epi >= 1) v += __ldg(&J.bias[n]);
                if (J.epi == 2) v = softplusf(v);
                stage[mloc * (TN + 1) + c0 + j] = v;
            }
        }
    }
    __syncthreads();

    for (int i = tid; i < 128 * TN; i += 256) {
        int ml = i / TN, n = i - ml * TN;
        float v = stage[ml * (TN + 1) + n];
        int gn = bn + n;
        if (J.outm == 1) {
            size_t o = (size_t)(bm + ml) * J.ldc + gn;
            __nv_bfloat16 h0, h1; split2(v, h0, h1);
            J.C0[o] = h0; J.C1[o] = h1;
        } else if (gn < J.Nreal) {
            size_t o = (size_t)(bm + ml) * J.ldc + gn;
            J.Cf[o] = v;
            if (gn < J.Ng) {
                const float* c = J.gc + gn * 5;
                float p = c[0] + v * (c[1] + v * (c[2] + v * (c[3] + v * c[4])));
                J.Cg[o] = 1.f / (1.f + __expf(-p));
            }
        }
    }
    __syncthreads();
    if (wid == 0) tmem_dealloc(tmem, TN);

#else  // ---------- SIMT fallback (generic PTX pass; never runs on sm_103a) ----------
    (void)smem;
    for (int i = tid; i < 128 * TN; i += 256) {
        int ml = i / TN, n = i - ml * TN;
        int m = bm + ml, gn = bn + n;
        float acc = 0.f;
        for (int kt = 0; kt < J.ktn; kt++) {
            int kb = (J.kt0 + kt) << 5;
            for (int k = kb; k < kb + 32; k++) {
                float a = __bfloat162float(J.A0[(size_t)m * J.lda + k]) +
                          __bfloat162float(J.A1[(size_t)m * J.lda + k]);
                float b = __bfloat162float(J.B0[(size_t)gn * J.ldb + k]) +
                          __bfloat162float(J.B1[(size_t)gn * J.ldb + k]);
                acc = fmaf(a, b, acc);
            }
        }
        if (J.epi >= 1) acc += J.bias[gn];
        if (J.epi == 2) acc = softplusf(acc);
        if (J.outm == 1) {
            size_t o = (size_t)m * J.ldc + gn;
            __nv_bfloat16 h0, h1; split2(acc, h0, h1);
            J.C0[o] = h0; J.C1[o] = h1;
        } else if (gn < J.Nreal) {
            size_t o = (size_t)m * J.ldc + gn;
            J.Cf[o] = acc;
            if (gn < J.Ng) {
                const float* c = J.gc + gn * 5;
                float p = c[0] + acc * (c[1] + acc * (c[2] + acc * (c[3] + acc * c[4])));
                J.Cg[o] = 1.f / (1.f + __expf(-p));
            }
        }
    }
#endif
}

// ---------------- final assembly ----------------
__global__ __launch_bounds__(128)
void heads_asm(const float* __restrict__ fout, const float* __restrict__ cout,
               const float* __restrict__ gout, float* __restrict__ out)
{
    const int b = blockIdx.x;
    const int t = threadIdx.x;
    __shared__ float fr[62], cr[62], sctx[CC];
    __shared__ float mx[2], lse[2];

    if (t < 62)       fr[t] = fout[(size_t)b * NF3 + DSE + t];
    else if (t < 124) cr[t - 62] = cout[(size_t)b * NC3 + CC + (t - 62)];
    if (t < CC) sctx[t] = cout[(size_t)b * NC3 + t];
    __syncthreads();

    if (t == 0) {
        float m = -1e30f;
        for (int i = 25; i < 37; i++) m = fmaxf(m, fr[i]);
        float s = 0.f;
        for (int i = 25; i < 37; i++) s += __expf(fr[i] - m);
        mx[0] = m; lse[0] = __logf(s);
    } else if (t == 32) {
        float m = -1e30f;
        for (int i = 25; i < 37; i++) m = fmaxf(m, cr[i]);
        float s = 0.f;
        for (int i = 25; i < 37; i++) s += __expf(cr[i] - m);
        mx[1] = m; lse[1] = __logf(s);
    }
    __syncthreads();

    float* o = out + (size_t)b * OUTW;
    const float* gr = gout + (size_t)b * NF3;
    for (int i = t; i < OUTW; i += 128) {
        float v;
        if (i < 25)        v = fr[i];
        else if (i < 37)   v = fr[i] - mx[0] - lse[0];
        else if (i < 62)   v = fr[i];
        else if (i < 289)  v = gr[i - 62];
        else if (i < 314)  v = cr[i - 289];
        else if (i < 326)  v = cr[25 + (i - 314)] - mx[1] - lse[1];
        else if (i < 351)  v = cr[37 + (i - 326)];
        else               v = sctx[i - 351];
        o[i] = v;
    }
}

// ---------------- launch ----------------
#define GETP2(name) \
    __nv_bfloat16 *name##0, *name##1; \
    cudaGetSymbolAddress((void**)&name##0, name##_0); \
    cudaGetSymbolAddress((void**)&name##1, name##_1);

extern "C" void kernel_launch(void* const* d_in, const int* in_sizes, int n_in,
                              void* d_out, int out_size)
{
    const float* se    = (const float*)d_in[0];
    const float* pz    = (const float*)d_in[1];
    const float* Wref  = (const float*)d_in[2];
    const float* fW1   = (const float*)d_in[3];
    const float* fb1   = (const float*)d_in[4];
    const float* fW2   = (const float*)d_in[5];
    const float* fb2   = (const float*)d_in[6];
    const float* fW3   = (const float*)d_in[7];
    const float* fb3   = (const float*)d_in[8];
    const float* gW1   = (const float*)d_in[9];
    const float* gb1   = (const float*)d_in[10];
    const float* gW2   = (const float*)d_in[11];
    const float* gb2   = (const float*)d_in[12];
    const float* Wland = (const float*)d_in[13];
    const float* Wshot = (const float*)d_in[14];
    const float* Wmove = (const float*)d_in[15];
    const float* cW1   = (const float*)d_in[16];
    const float* cb1   = (const float*)d_in[17];
    const float* cW2   = (const float*)d_in[18];
    const float* cb2   = (const float*)d_in[19];
    const float* cW3   = (const float*)d_in[20];
    const float* cb3   = (const float*)d_in[21];
    const float* cWl   = (const float*)d_in[22];
    const float* cWs   = (const float*)d_in[23];
    const float* cWm   = (const float*)d_in[24];
    float* out = (float*)d_out;

    GETP2(g_Ac)  GETP2(g_ch1) GETP2(g_ch2) GETP2(g_fin) GETP2(g_fh1) GETP2(g_fh2)
    GETP2(g_Br)  GETP2(g_c1w) GETP2(g_c2w) GETP2(g_c3w) GETP2(g_f1w) GETP2(g_f2w) GETP2(g_f3w)

    float *fout, *cout, *gout, *gc, *fbias, *cbias, *ep0, *ep1, *ep2;
    cudaGetSymbolAddress((void**)&fout,  d_fout);
    cudaGetSymbolAddress((void**)&cout,  d_cout);
    cudaGetSymbolAddress((void**)&gout,  d_gout);
    cudaGetSymbolAddress((void**)&gc,    d_gc);
    cudaGetSymbolAddress((void**)&fbias, d_fbias);
    cudaGetSymbolAddress((void**)&cbias, d_cbias);
    cudaGetSymbolAddress((void**)&ep0,   d_ep0);
    cudaGetSymbolAddress((void**)&ep1,   d_ep1);
    cudaGetSymbolAddress((void**)&ep2,   d_ep2);

    cudaFuncSetAttribute(tc_gemm_multi, cudaFuncAttributeMaxDynamicSharedMemorySize, SMB);
    cudaFuncSetAttribute(mid_kernel, cudaFuncAttributeMaxDynamicSharedMemorySize, MID_SMEM);

    const int MT = BB / 128;   // 32
    C5 cz = {};

    // L0: fused front (act || wref || cW1)
    front_kernel<<<ACT_CTAS + WREF_CTAS + 32, 256>>>(
        pz, se, Wref, cW1, g_Ac0, g_Ac1, g_Br0, g_Br1, g_c1w0, g_c1w1);

    // L1: enc split-K x3 || ch1 || conv x5
    {
        GJob e0 = {g_Ac0, g_Ac1, g_Br0, g_Br1, nullptr, ep0, nullptr, nullptr,
                   nullptr, nullptr, KCOMB, KCOMB, DSEP, DSEP, 0, 0, 61, 0, 0, 2};
        GJob e1 = e0; e1.Cf = ep1; e1.kt0 = 61;  e1.ktn = 61;
        GJob e2 = e0; e2.Cf = ep2; e2.kt0 = 122; e2.ktn = 60;
        GJob ch1 = {g_Ac0, g_Ac1, g_c1w0, g_c1w1, cb1, nullptr, g_ch10, g_ch11,
                    nullptr, nullptr, KCOMB, 64, HH, HH, 0, 0, 2, 2, 1, 8};
        C5 cv;
        cv.j[0] = {cW2, g_c2w0, g_c2w1, HH, HH, HH, 16, 512};
        cv.j[1] = {cW3, g_c3w0, g_c3w1, HH, CC, HH, 16, 512 + 64};
        cv.j[2] = {fW1, g_f1w0, g_f1w1, DSE, HH, DSEP, 4, 512 + 64 + 128};
        cv.j[3] = {fW2, g_f2w0, g_f2w1, HH, HH, HH, 16, 512 + 64 + 128 + 512};
        cv.j[4] = {fW3, g_f3w0, g_f3w1, HH, DSE, HH, 16, 512 + 64 + 128 + 512 + 192};
        const int n3 = 64 + 64 + 64 + 8 * MT;   // 448
        tc_gemm_multi<<<n3 + NCONV, 256, SMB>>>(e0, e1, e2, ch1, 64, 128, 192, n3, cv);
    }

    // L2: reduce || fast prep (after conv zero-fill; before weight consumers)
    mid_kernel<<<RED_CTAS + 64 + DSE + 2, 256, MID_SMEM>>>(
        ep0, ep1, ep2, g_fin0, g_fin1,
        fW3, cW3, Wland, Wshot, Wmove, cWl, cWs, cWm, fb3, cb3,
        gW1, gb1, gW2, gb2,
        g_f3w0, g_f3w1, g_c3w0, g_c3w1, fbias, cbias, gc);

    // L3: ch2 || f1
    {
        GJob ch2 = {g_ch10, g_ch11, g_c2w0, g_c2w1, cb2, nullptr, g_ch20, g_ch21,
                    nullptr, nullptr, HH, HH, HH, HH, 0, 0, 32, 2, 1, 8};
        GJob f1  = {g_fin0, g_fin1, g_f1w0, g_f1w1, fb1, nullptr, g_fh10, g_fh11,
                    nullptr, nullptr, DSEP, DSEP, HH, HH, 0, 0, 8, 2, 1, 8};
        tc_gemm_multi<<<16 * MT, 256, SMB>>>(ch2, f1, ch2, f1, 8 * MT, 16 * MT, 16 * MT, 16 * MT, cz);
    }
    // L4: f2 || c3ext
    {
        GJob f2 = {g_fh10, g_fh11, g_f2w0, g_f2w1, fb2, nullptr, g_fh20, g_fh21,
                   nullptr, nullptr, HH, HH, HH, HH, 0, 0, 32, 2, 1, 8};
        GJob c3 = {g_ch20, g_ch21, g_c3w0, g_c3w1, cbias, cout, nullptr, nullptr,
                   nullptr, nullptr, HH, HH, NC3, CC + 62, 0, 0, 32, 1, 0, 1};
        tc_gemm_multi<<<9 * MT, 256, SMB>>>(f2, c3, f2, c3, 8 * MT, 9 * MT, 9 * MT, 9 * MT, cz);
    }
    // L5: f3ext (latent + heads + fused g-poly)
    {
        GJob f3 = {g_fh20, g_fh21, g_f3w0, g_f3w1, fbias, fout, nullptr, nullptr,
                   gc, gout, HH, HH, NF3, DSE + 62, DSE, 0, 32, 1, 0, 3};
        tc_gemm_multi<<<3 * MT, 256, SMB>>>(f3, f3, f3, f3, 3 * MT, 3 * MT, 3 * MT, 3 * MT, cz);
    }
    // L6: assembly
    heads_asm<<<BB, 128>>>(fout, cout, gout, out);
}